// round 11
// baseline (speedup 1.0000x reference)
#include <cuda_runtime.h>
#include <cstdint>
#include <math.h>

#define H      128
#define HH     (H * H)
#define KNB    48
#define NN     2048
#define BNTOT  4096
#define XP     132          // activation tile pitch (floats)
#define WP     68           // weight tile pitch (floats)

// weight matrix slots in g_Wt (all 128x128 [n][k] natural order, tf32-rounded)
#define W_E1   0
#define W_2T   1
#define W_3T   2
#define W_11E  3
#define W_12T  4
#define W_13T  5
#define W_1V   6
#define W_1G   7
#define W_1A   8
#define W_11V  9
#define W_11G  10
#define W_INT  11   // 11..14: W_in^T chunks
#define W_OUTT 15   // 15..18: W_out^T chunks

__device__ float g_Wt[19 * HH];
__device__ float g_D1[BNTOT * H];
__device__ float g_P1[BNTOT * H];
__device__ float g_D2[BNTOT * H];
__device__ float g_P2[BNTOT * H];
__device__ float g_hV1[BNTOT * H];

__device__ __forceinline__ float to_tf32(float x) {
    uint32_t u;
    asm("cvt.rna.tf32.f32 %0, %1;" : "=r"(u) : "f"(x));
    return __uint_as_float(u);
}

__device__ __forceinline__ float gelu_exact(float x) {
    return 0.5f * x * (1.0f + erff(x * 0.70710678118654752f));
}

__device__ __forceinline__ void mma_tf32(float d[4], const uint32_t a[4], const uint32_t b[2]) {
    asm volatile("mma.sync.aligned.m16n8k8.row.col.f32.tf32.tf32.f32 "
                 "{%0,%1,%2,%3}, {%4,%5,%6,%7}, {%8,%9}, {%0,%1,%2,%3};"
                 : "+f"(d[0]), "+f"(d[1]), "+f"(d[2]), "+f"(d[3])
                 : "r"(a[0]), "r"(a[1]), "r"(a[2]), "r"(a[3]), "r"(b[0]), "r"(b[1]));
}

// ================= chained-MLP building blocks (128-thread kernels) =================

// cp.async stage of one 64-k half of a [n][k] weight matrix into sW (pitch WP)
__device__ __forceinline__ void stage_async(float* sWbuf, const float* __restrict__ Wg,
                                            int h, int tid) {
    uint32_t base = (uint32_t)__cvta_generic_to_shared(sWbuf);
#pragma unroll
    for (int i = 0; i < 16; i++) {
        int idx = tid + 128 * i;
        int n = idx >> 4, q = idx & 15;
        asm volatile("cp.async.cg.shared.global [%0], [%1], 16;"
                     :: "r"(base + (uint32_t)((n * WP + q * 4) * 4)),
                        "l"(Wg + n * H + h * 64 + q * 4));
    }
    asm volatile("cp.async.commit_group;");
}

// one 64x128x(64-k-half) MMA sweep; A regs indexed by absolute k-group
template <int HF>
__device__ __forceinline__ void mma_half(const float* __restrict__ sWbuf, int lane,
                                         const uint32_t A[16][4], float D[16][4]) {
    const int lr = lane >> 2, lc = lane & 3;
    const float* sWb = sWbuf + lr * WP + 2 * lc;
#pragma unroll
    for (int g = 0; g < 8; g++) {
#pragma unroll
        for (int nt = 0; nt < 16; nt++) {
            float2 bv = *(const float2*)(sWb + nt * (8 * WP) + g * 8);
            uint32_t b[2] = {__float_as_uint(bv.x), __float_as_uint(bv.y)};
            mma_tf32(D[nt], A[HF * 8 + g], b);
        }
    }
}

__device__ __forceinline__ void zero_D(float D[16][4]) {
#pragma unroll
    for (int nt = 0; nt < 16; nt++)
#pragma unroll
        for (int q = 0; q < 4; q++) D[nt][q] = 0.f;
}

// ================= 256-thread GEMM for pre/ffn (slot convention, natural weights) ====

__device__ __forceinline__ void stage_W_half(float* __restrict__ sW,
                                             const float* __restrict__ Wg, int h, int tid) {
#pragma unroll
    for (int i = 0; i < 8; i++) {
        int idx = tid + 256 * i;
        int n = idx >> 4, q = idx & 15;
        float4 v = *(const float4*)(Wg + n * H + h * 64 + q * 4);
        *(float4*)(sW + n * WP + q * 4) = v;
    }
}

__device__ __forceinline__ void gemm256(const float* __restrict__ sX, float* __restrict__ sW,
                                        const float* __restrict__ Wg, int tid,
                                        float acc[2][8][4]) {
    const int w = tid >> 5, lane = tid & 31;
    const int wm = w & 3, wn = w >> 2;
    const int lr = lane >> 2, lc = lane & 3;
    const float* sXw = sX + (wm * 32 + lr) * XP + 2 * lc;
    const float* sWb = sW + (wn * 64 + lr) * WP + 2 * lc;
#pragma unroll
    for (int h = 0; h < 2; h++) {
        __syncthreads();
        stage_W_half(sW, Wg, h, tid);
        __syncthreads();
#pragma unroll
        for (int k8 = 0; k8 < 8; k8++) {
            const int kl = k8 * 8;
            uint32_t a[2][4];
#pragma unroll
            for (int mt = 0; mt < 2; mt++) {
                const float* ap = sXw + mt * (16 * XP) + h * 64 + kl;
                float2 lo = *(const float2*)(ap);
                float2 hi = *(const float2*)(ap + 8 * XP);
                a[mt][0] = __float_as_uint(lo.x);
                a[mt][2] = __float_as_uint(lo.y);
                a[mt][1] = __float_as_uint(hi.x);
                a[mt][3] = __float_as_uint(hi.y);
            }
#pragma unroll
            for (int nt = 0; nt < 8; nt++) {
                float2 bv = *(const float2*)(sWb + nt * (8 * WP) + kl);
                uint32_t b[2] = {__float_as_uint(bv.x), __float_as_uint(bv.y)};
                mma_tf32(acc[0][nt], a[0], b);
                mma_tf32(acc[1][nt], a[1], b);
            }
        }
    }
}

__device__ __forceinline__ void gemm32(const float* __restrict__ sX, float* __restrict__ sW,
                                       const float* __restrict__ Wg, int tid,
                                       float acc[2][2][4]) {
    const int w = tid >> 5, lane = tid & 31;
    const int lr = lane >> 2, lc = lane & 3;
    const float* sXw = sX + lr * XP + 2 * lc;
    const float* sWb = sW + (w * 16 + lr) * WP + 2 * lc;
#pragma unroll
    for (int h = 0; h < 2; h++) {
        __syncthreads();
        stage_W_half(sW, Wg, h, tid);
        __syncthreads();
#pragma unroll
        for (int k8 = 0; k8 < 8; k8++) {
            const int kl = k8 * 8;
            uint32_t a[2][4];
#pragma unroll
            for (int mt = 0; mt < 2; mt++) {
                const float* ap = sXw + mt * (16 * XP) + h * 64 + kl;
                float2 lo = *(const float2*)(ap);
                float2 hi = *(const float2*)(ap + 8 * XP);
                a[mt][0] = __float_as_uint(lo.x);
                a[mt][2] = __float_as_uint(lo.y);
                a[mt][1] = __float_as_uint(hi.x);
                a[mt][3] = __float_as_uint(hi.y);
            }
#pragma unroll
            for (int nt = 0; nt < 2; nt++) {
                float2 bv = *(const float2*)(sWb + nt * (8 * WP) + kl);
                uint32_t b[2] = {__float_as_uint(bv.x), __float_as_uint(bv.y)};
                mma_tf32(acc[0][nt], a[0], b);
                mma_tf32(acc[1][nt], a[1], b);
            }
        }
    }
}

__device__ __forceinline__ void zero_acc(float acc[2][8][4]) {
#pragma unroll
    for (int mt = 0; mt < 2; mt++)
#pragma unroll
        for (int nt = 0; nt < 8; nt++)
#pragma unroll
            for (int q = 0; q < 4; q++) acc[mt][nt][q] = 0.f;
}

__device__ __forceinline__ void zero_acc32(float acc[2][2][4]) {
#pragma unroll
    for (int mt = 0; mt < 2; mt++)
#pragma unroll
        for (int nt = 0; nt < 2; nt++)
#pragma unroll
            for (int q = 0; q < 4; q++) acc[mt][nt][q] = 0.f;
}

__device__ __forceinline__ void epi_bias_gelu32(float* __restrict__ dst, int tid,
                                                const float acc[2][2][4],
                                                const float* __restrict__ bias) {
    const int w = tid >> 5, lane = tid & 31;
    const int lr = lane >> 2, lc = lane & 3;
    float* cx = dst + lr * XP + w * 16 + 2 * lc;
#pragma unroll
    for (int nt = 0; nt < 2; nt++) {
        float2 bv = *(const float2*)(bias + w * 16 + nt * 8 + 2 * lc);
#pragma unroll
        for (int mt = 0; mt < 2; mt++) {
            *(float2*)(cx + mt * (16 * XP) + nt * 8) =
                make_float2(to_tf32(gelu_exact(acc[mt][nt][0] + bv.x)),
                            to_tf32(gelu_exact(acc[mt][nt][1] + bv.y)));
            *(float2*)(cx + mt * (16 * XP) + 8 * XP + nt * 8) =
                make_float2(to_tf32(gelu_exact(acc[mt][nt][2] + bv.x)),
                            to_tf32(gelu_exact(acc[mt][nt][3] + bv.y)));
        }
    }
}

__device__ __forceinline__ void store_acc32(float* __restrict__ dst, int tid,
                                            const float acc[2][2][4]) {
    const int w = tid >> 5, lane = tid & 31;
    const int lr = lane >> 2, lc = lane & 3;
    float* cx = dst + lr * XP + w * 16 + 2 * lc;
#pragma unroll
    for (int mt = 0; mt < 2; mt++)
#pragma unroll
        for (int nt = 0; nt < 2; nt++) {
            *(float2*)(cx + mt * (16 * XP) + nt * 8) =
                make_float2(acc[mt][nt][0], acc[mt][nt][1]);
            *(float2*)(cx + mt * (16 * XP) + 8 * XP + nt * 8) =
                make_float2(acc[mt][nt][2], acc[mt][nt][3]);
        }
}

__device__ __forceinline__ void epi_to_global(float* __restrict__ gdst, int p0, int tid,
                                              const float acc[2][8][4],
                                              const float* __restrict__ bias) {
    const int w = tid >> 5, lane = tid & 31;
    const int wm = w & 3, wn = w >> 2;
    const int lr = lane >> 2, lc = lane & 3;
#pragma unroll
    for (int nt = 0; nt < 8; nt++) {
        int col = wn * 64 + nt * 8 + 2 * lc;
        float2 bv = bias ? *(const float2*)(bias + col) : make_float2(0.f, 0.f);
#pragma unroll
        for (int mt = 0; mt < 2; mt++) {
            int r0 = wm * 32 + mt * 16 + lr;
            *(float2*)(gdst + (size_t)(p0 + r0) * H + col) =
                make_float2(acc[mt][nt][0] + bv.x, acc[mt][nt][1] + bv.y);
            *(float2*)(gdst + (size_t)(p0 + r0 + 8) * H + col) =
                make_float2(acc[mt][nt][2] + bv.x, acc[mt][nt][3] + bv.y);
        }
    }
}

// ---------------- prep weights: transpose/fold + tf32, natural [n][k] ----------------
__global__ void prep_weights(const float* __restrict__ W1, const float* __restrict__ W2,
                             const float* __restrict__ W3, const float* __restrict__ W11,
                             const float* __restrict__ W12, const float* __restrict__ W13,
                             const float* __restrict__ W_in, const float* __restrict__ W_out) {
    int idx = blockIdx.x * 256 + threadIdx.x;
    if (idx >= 19 * HH) return;
    int m = idx / HH;
    int r = (idx >> 7) & 127;
    int c = idx & 127;
    float v;
    switch (m) {
        case W_E1:  v = W1[(128 + c) * H + r] + W1[(384 + c) * H + r]; break;
        case W_2T:  v = W2[c * H + r]; break;
        case W_3T:  v = W3[c * H + r]; break;
        case W_11E: v = W11[(128 + c) * H + r]; break;
        case W_12T: v = W12[c * H + r]; break;
        case W_13T: v = W13[c * H + r]; break;
        case W_1V:  v = W1[c * H + r]; break;
        case W_1G:  v = W1[(256 + c) * H + r]; break;
        case W_1A:  v = W1[(512 + c) * H + r]; break;
        case W_11V: v = W11[c * H + r]; break;
        case W_11G: v = W11[(256 + c) * H + r]; break;
        default:
            if (m < W_OUTT) {
                int nc = m - W_INT;
                v = W_in[c * 512 + nc * 128 + r];
            } else {
                int kc = m - W_OUTT;
                v = W_out[(kc * 128 + c) * H + r];
            }
            break;
    }
    g_Wt[m * HH + r * H + c] = to_tf32(v);
}

// ---------------- pre1 (grid 32x2) ----------------
__global__ void __launch_bounds__(256)
pre1_mma(const float* __restrict__ hV, const float* __restrict__ hVa,
         const float* __restrict__ b1) {
    extern __shared__ float smf[];
    float* sXa = smf;
    float* sXb = smf + 16896;
    float* sW  = smf + 33792;
    const int tid = threadIdx.x;
    const int p0 = blockIdx.x * 128;
    const int z = blockIdx.y;
    const int r = tid >> 1, ch = (tid & 1) * 64;

    {
        const float* a = hV + (size_t)(p0 + r) * H + ch;
        float* xa = sXa + r * XP + ch;
#pragma unroll
        for (int c = 0; c < 64; c += 4) {
            float4 v = *(const float4*)(a + c);
            xa[c] = to_tf32(v.x); xa[c+1] = to_tf32(v.y); xa[c+2] = to_tf32(v.z); xa[c+3] = to_tf32(v.w);
        }
        if (z == 1) {
            const float* b = hVa + (size_t)(p0 + r) * H + ch;
            float* xb = sXb + r * XP + ch;
#pragma unroll
            for (int c = 0; c < 64; c += 4) {
                float4 u = *(const float4*)(b + c);
                xb[c] = to_tf32(u.x); xb[c+1] = to_tf32(u.y); xb[c+2] = to_tf32(u.z); xb[c+3] = to_tf32(u.w);
            }
        }
    }

    float acc[2][8][4];
    zero_acc(acc);
    if (z == 0) {
        gemm256(sXa, sW, g_Wt + W_1V * HH, tid, acc);
        epi_to_global(g_D1, p0, tid, acc, b1);
    } else {
        gemm256(sXa, sW, g_Wt + W_1G * HH, tid, acc);
        gemm256(sXb, sW, g_Wt + W_1A * HH, tid, acc);
        epi_to_global(g_P1, p0, tid, acc, (const float*)nullptr);
    }
}

// ---------------- pre2 (grid 32x2) ----------------
__global__ void __launch_bounds__(256)
pre2_mma(const float* __restrict__ hVf, const float* __restrict__ b11) {
    extern __shared__ float smf[];
    float* sXa = smf;
    float* sW  = smf + 16896;
    const int tid = threadIdx.x;
    const int p0 = blockIdx.x * 128;
    const int z = blockIdx.y;
    const int r = tid >> 1, ch = (tid & 1) * 64;

    {
        const float* a = hVf + (size_t)(p0 + r) * H + ch;
        float* xa = sXa + r * XP + ch;
#pragma unroll
        for (int c = 0; c < 64; c += 4) {
            float4 v = *(const float4*)(a + c);
            xa[c] = to_tf32(v.x); xa[c+1] = to_tf32(v.y); xa[c+2] = to_tf32(v.z); xa[c+3] = to_tf32(v.w);
        }
    }

    float acc[2][8][4];
    zero_acc(acc);
    if (z == 0) {
        gemm256(sXa, sW, g_Wt + W_11V * HH, tid, acc);
        epi_to_global(g_D2, p0, tid, acc, b11);
    } else {
        gemm256(sXa, sW, g_Wt + W_11G * HH, tid, acc);
        epi_to_global(g_P2, p0, tid, acc, (const float*)nullptr);
    }
}

// ================= node/edge chained kernels (128 threads, 4 nodes/CTA) =================
// smem (floats): sX 0..8448 | sW0 8448..17152 | sW1 17152..25856 | sD 25856..26368 |
//   sAcc 26368..26880 | sB2 26880..27008 | sB3 27008..27136 | sMask 27136..27200 |
//   sIdx 27200..27392 (int) | sRed 27392..27400
#define SMEM_CH 27400

// ---------------- node message MLP + sum_K + LN1 ----------------
__global__ void __launch_bounds__(128)
node_mma_kernel(const float* __restrict__ hV, const float* __restrict__ hE,
                const float* __restrict__ b2, const float* __restrict__ b3,
                const float* __restrict__ g1, const float* __restrict__ be1,
                const float* __restrict__ maskA, const int* __restrict__ Eidx) {
    extern __shared__ float smf[];
    float* sX    = smf;
    float* sW0   = smf + 8448;
    float* sW1   = smf + 17152;
    float* sD    = smf + 25856;
    float* sAcc  = smf + 26368;
    float* sB2   = smf + 26880;
    float* sB3   = smf + 27008;
    float* sMask = smf + 27136;
    int*   sIdx  = (int*)(smf + 27200);
    float* sRed  = smf + 27392;
    float* sWbuf[2] = {sW0, sW1};

    const int tid = threadIdx.x;
    const int w = tid >> 5, lane = tid & 31;
    const int lr = lane >> 2, lc = lane & 3;
    const int P0 = blockIdx.x * 4;        // node base
    const int E0 = P0 * KNB;              // edge base
    const int bb = P0 >> 11;
    const float* P1b = g_P1 + (size_t)bb * NN * H;

    const float* Wseq[6] = {g_Wt + W_E1 * HH, g_Wt + W_E1 * HH,
                            g_Wt + W_2T * HH, g_Wt + W_2T * HH,
                            g_Wt + W_3T * HH, g_Wt + W_3T * HH};
    stage_async(sW0, Wseq[0], 0, tid);

    for (int i = tid; i < 512; i += 128) {
        sD[i] = g_D1[(size_t)P0 * H + i];
        sAcc[i] = 0.f;
    }
    sB2[tid] = b2[tid];
    sB3[tid] = b3[tid];
    for (int i = tid; i < 192; i += 128) sIdx[i] = Eidx[(size_t)E0 + i];

    uint32_t A[16][4];
    float D[16][4];
    zero_D(D);

    const int r0 = w * 16 + lr;
    const int r1 = r0 + 8;

    for (int t = 0; t < 3; t++) {
        const int e0 = E0 + t * 64;
        __syncthreads();    // sX free (prev segsum done)
        {   // stage hE tile (tf32) + mask
            int rr = tid >> 1, ch = (tid & 1) * 64;
            const float* a = hE + (size_t)(e0 + rr) * H + ch;
            float* x = sX + rr * XP + ch;
#pragma unroll
            for (int c = 0; c < 64; c += 4) {
                float4 v = *(const float4*)(a + c);
                x[c] = to_tf32(v.x); x[c+1] = to_tf32(v.y);
                x[c+2] = to_tf32(v.z); x[c+3] = to_tf32(v.w);
            }
            if (tid < 64) sMask[tid] = maskA[e0 + tid];
        }

#pragma unroll
        for (int s = 0; s < 6; s++) {
            const bool lastH = (t == 2) && (s == 5);
            if (!lastH) {
                stage_async(sWbuf[(s + 1) & 1], Wseq[(s + 1) % 6], (s + 1) & 1, tid);
                asm volatile("cp.async.wait_group 1;");
            } else {
                asm volatile("cp.async.wait_group 0;");
            }
            __syncthreads();
            if (s == 0) {
#pragma unroll
                for (int g = 0; g < 16; g++) {
                    float2 u0 = *(const float2*)(sX + r0 * XP + g * 8 + 2 * lc);
                    float2 u1 = *(const float2*)(sX + r1 * XP + g * 8 + 2 * lc);
                    A[g][0] = __float_as_uint(u0.x);
                    A[g][2] = __float_as_uint(u0.y);
                    A[g][1] = __float_as_uint(u1.x);
                    A[g][3] = __float_as_uint(u1.y);
                }
            }
            if (s & 1) mma_half<1>(sWbuf[s & 1], lane, A, D);
            else       mma_half<0>(sWbuf[s & 1], lane, A, D);
            __syncthreads();

            if (s == 1) {
                // epi1: A = tf32(gelu(D + D1[node] + P1[src]))
                const int src0 = sIdx[t * 64 + r0];
                const int src1 = sIdx[t * 64 + r1];
                const int nl0 = (t * 64 + r0) / KNB;
                const int nl1 = (t * 64 + r1) / KNB;
                const float* p0 = P1b + (size_t)src0 * H;
                const float* p1 = P1b + (size_t)src1 * H;
                const float* d0 = sD + nl0 * H;
                const float* d1 = sD + nl1 * H;
#pragma unroll
                for (int nt = 0; nt < 16; nt++) {
                    int col = nt * 8 + 2 * lc;
                    float2 pa = *(const float2*)(p0 + col);
                    float2 pb = *(const float2*)(p1 + col);
                    float2 da = *(const float2*)(d0 + col);
                    float2 db = *(const float2*)(d1 + col);
                    A[nt][0] = __float_as_uint(to_tf32(gelu_exact(D[nt][0] + da.x + pa.x)));
                    A[nt][2] = __float_as_uint(to_tf32(gelu_exact(D[nt][1] + da.y + pa.y)));
                    A[nt][1] = __float_as_uint(to_tf32(gelu_exact(D[nt][2] + db.x + pb.x)));
                    A[nt][3] = __float_as_uint(to_tf32(gelu_exact(D[nt][3] + db.y + pb.y)));
                    D[nt][0] = D[nt][1] = D[nt][2] = D[nt][3] = 0.f;
                }
            } else if (s == 3) {
                // epi2: A = tf32(gelu(D + b2))
#pragma unroll
                for (int nt = 0; nt < 16; nt++) {
                    float2 bv = *(const float2*)(sB2 + nt * 8 + 2 * lc);
                    A[nt][0] = __float_as_uint(to_tf32(gelu_exact(D[nt][0] + bv.x)));
                    A[nt][2] = __float_as_uint(to_tf32(gelu_exact(D[nt][1] + bv.y)));
                    A[nt][1] = __float_as_uint(to_tf32(gelu_exact(D[nt][2] + bv.x)));
                    A[nt][3] = __float_as_uint(to_tf32(gelu_exact(D[nt][3] + bv.y)));
                    D[nt][0] = D[nt][1] = D[nt][2] = D[nt][3] = 0.f;
                }
            } else if (s == 5) {
                // epi3: masked message -> sX
                float mk0 = sMask[r0], mk1 = sMask[r1];
#pragma unroll
                for (int nt = 0; nt < 16; nt++) {
                    float2 bv = *(const float2*)(sB3 + nt * 8 + 2 * lc);
                    *(float2*)(sX + r0 * XP + nt * 8 + 2 * lc) =
                        make_float2(mk0 * (D[nt][0] + bv.x), mk0 * (D[nt][1] + bv.y));
                    *(float2*)(sX + r1 * XP + nt * 8 + 2 * lc) =
                        make_float2(mk1 * (D[nt][2] + bv.x), mk1 * (D[nt][3] + bv.y));
                    D[nt][0] = D[nt][1] = D[nt][2] = D[nt][3] = 0.f;
                }
            }
        }
        __syncthreads();
        // segment-sum: thread col = tid, rows 0..63 with node boundaries at 48
        {
            int nl = (t * 64) / KNB;
            int nxt = (nl + 1) * KNB - t * 64;
            float a = 0.f;
            for (int rr = 0; rr < 64; rr++) {
                if (rr == nxt) { sAcc[nl * 128 + tid] += a; nl++; nxt += KNB; a = 0.f; }
                a += sX[rr * XP + tid];
            }
            sAcc[nl * 128 + tid] += a;
        }
    }
    __syncthreads();

    // LN1 over 4 nodes (128 threads, thread = col)
    for (int n = 0; n < 4; n++) {
        float u = hV[(size_t)(P0 + n) * H + tid] + sAcc[n * 128 + tid] * (1.0f / 30.0f);
        float s = u;
#pragma unroll
        for (int off = 16; off > 0; off >>= 1) s += __shfl_xor_sync(0xffffffffu, s, off);
        if (lane == 0) sRed[w] = s;
        __syncthreads();
        float mean = (sRed[0] + sRed[1] + sRed[2] + sRed[3]) * (1.0f / H);
        float d = u - mean;
        float v2 = d * d;
#pragma unroll
        for (int off = 16; off > 0; off >>= 1) v2 += __shfl_xor_sync(0xffffffffu, v2, off);
        if (lane == 0) sRed[4 + w] = v2;
        __syncthreads();
        float var = (sRed[4] + sRed[5] + sRed[6] + sRed[7]) * (1.0f / H);
        g_hV1[(size_t)(P0 + n) * H + tid] = d * rsqrtf(var + 1e-5f) * g1[tid] + be1[tid];
        __syncthreads();
    }
}

// ---------------- edge update MLP + LN3 ----------------
__global__ void __launch_bounds__(128)
edge_mma_kernel(const float* __restrict__ hE,
                const float* __restrict__ b12, const float* __restrict__ b13,
                const float* __restrict__ g3, const float* __restrict__ be3,
                const int* __restrict__ Eidx, float* __restrict__ outE) {
    extern __shared__ float smf[];
    float* sX    = smf;
    float* sW0   = smf + 8448;
    float* sW1   = smf + 17152;
    float* sD    = smf + 25856;
    float* sB12  = smf + 26880;
    int*   sIdx  = (int*)(smf + 27200);
    float* sWbuf[2] = {sW0, sW1};

    const int tid = threadIdx.x;
    const int w = tid >> 5, lane = tid & 31;
    const int lr = lane >> 2, lc = lane & 3;
    const int P0 = blockIdx.x * 4;
    const int E0 = P0 * KNB;
    const int bb = P0 >> 11;
    const float* P2b = g_P2 + (size_t)bb * NN * H;

    const float* Wseq[6] = {g_Wt + W_11E * HH, g_Wt + W_11E * HH,
                            g_Wt + W_12T * HH, g_Wt + W_12T * HH,
                            g_Wt + W_13T * HH, g_Wt + W_13T * HH};
    stage_async(sW0, Wseq[0], 0, tid);

    for (int i = tid; i < 512; i += 128) sD[i] = g_D2[(size_t)P0 * H + i];
    sB12[tid] = b12[tid];
    for (int i = tid; i < 192; i += 128) sIdx[i] = Eidx[(size_t)E0 + i];

    float b13v[4], g3v[4], be3v[4];
#pragma unroll
    for (int q = 0; q < 4; q++) {
        b13v[q] = b13[lane + 32 * q];
        g3v[q]  = g3[lane + 32 * q];
        be3v[q] = be3[lane + 32 * q];
    }

    uint32_t A[16][4];
    float D[16][4];
    zero_D(D);

    const int r0 = w * 16 + lr;
    const int r1 = r0 + 8;

    for (int t = 0; t < 3; t++) {
        const int e0 = E0 + t * 64;
        __syncthreads();
        {
            int rr = tid >> 1, ch = (tid & 1) * 64;
            const float* a = hE + (size_t)(e0 + rr) * H + ch;
            float* x = sX + rr * XP + ch;
#pragma unroll
            for (int c = 0; c < 64; c += 4) {
                float4 v = *(const float4*)(a + c);
                x[c] = to_tf32(v.x); x[c+1] = to_tf32(v.y);
                x[c+2] = to_tf32(v.z); x[c+3] = to_tf32(v.w);
            }
        }

#pragma unroll
        for (int s = 0; s < 6; s++) {
            const bool lastH = (t == 2) && (s == 5);
            if (!lastH) {
                stage_async(sWbuf[(s + 1) & 1], Wseq[(s + 1) % 6], (s + 1) & 1, tid);
                asm volatile("cp.async.wait_group 1;");
            } else {
                asm volatile("cp.async.wait_group 0;");
            }
            __syncthreads();
            if (s == 0) {
#pragma unroll
                for (int g = 0; g < 16; g++) {
                    float2 u0 = *(const float2*)(sX + r0 * XP + g * 8 + 2 * lc);
                    float2 u1 = *(const float2*)(sX + r1 * XP + g * 8 + 2 * lc);
                    A[g][0] = __float_as_uint(u0.x);
                    A[g][2] = __float_as_uint(u0.y);
                    A[g][1] = __float_as_uint(u1.x);
                    A[g][3] = __float_as_uint(u1.y);
                }
            }
            if (s & 1) mma_half<1>(sWbuf[s & 1], lane, A, D);
            else       mma_half<0>(sWbuf[s & 1], lane, A, D);
            __syncthreads();

            if (s == 1) {
                const int src0 = sIdx[t * 64 + r0];
                const int src1 = sIdx[t * 64 + r1];
                const int nl0 = (t * 64 + r0) / KNB;
                const int nl1 = (t * 64 + r1) / KNB;
                const float* p0 = P2b + (size_t)src0 * H;
                const float* p1 = P2b + (size_t)src1 * H;
                const float* d0 = sD + nl0 * H;
                const float* d1 = sD + nl1 * H;
#pragma unroll
                for (int nt = 0; nt < 16; nt++) {
                    int col = nt * 8 + 2 * lc;
                    float2 pa = *(const float2*)(p0 + col);
                    float2 pb = *(const float2*)(p1 + col);
                    float2 da = *(const float2*)(d0 + col);
                    float2 db = *(const float2*)(d1 + col);
                    A[nt][0] = __float_as_uint(to_tf32(gelu_exact(D[nt][0] + da.x + pa.x)));
                    A[nt][2] = __float_as_uint(to_tf32(gelu_exact(D[nt][1] + da.y + pa.y)));
                    A[nt][1] = __float_as_uint(to_tf32(gelu_exact(D[nt][2] + db.x + pb.x)));
                    A[nt][3] = __float_as_uint(to_tf32(gelu_exact(D[nt][3] + db.y + pb.y)));
                    D[nt][0] = D[nt][1] = D[nt][2] = D[nt][3] = 0.f;
                }
            } else if (s == 3) {
#pragma unroll
                for (int nt = 0; nt < 16; nt++) {
                    float2 bv = *(const float2*)(sB12 + nt * 8 + 2 * lc);
                    A[nt][0] = __float_as_uint(to_tf32(gelu_exact(D[nt][0] + bv.x)));
                    A[nt][2] = __float_as_uint(to_tf32(gelu_exact(D[nt][1] + bv.y)));
                    A[nt][1] = __float_as_uint(to_tf32(gelu_exact(D[nt][2] + bv.x)));
                    A[nt][3] = __float_as_uint(to_tf32(gelu_exact(D[nt][3] + bv.y)));
                    D[nt][0] = D[nt][1] = D[nt][2] = D[nt][3] = 0.f;
                }
            } else if (s == 5) {
                // epi3: raw message -> sX (b13 + residual folded into LN3)
#pragma unroll
                for (int nt = 0; nt < 16; nt++) {
                    *(float2*)(sX + r0 * XP + nt * 8 + 2 * lc) =
                        make_float2(D[nt][0], D[nt][1]);
                    *(float2*)(sX + r1 * XP + nt * 8 + 2 * lc) =
                        make_float2(D[nt][2], D[nt][3]);
                    D[nt][0] = D[nt][1] = D[nt][2] = D[nt][3] = 0.f;
                }
            }
        }
        __syncthreads();
        // LN3 with fused b13 + hE residual: each warp 16 rows
        for (int rr = w * 16; rr < w * 16 + 16; rr++) {
            const float* he = hE + (size_t)(e0 + rr) * H;
            float v[4];
            float ssum = 0.f;
#pragma unroll
            for (int q = 0; q < 4; q++) {
                v[q] = sX[rr * XP + lane + 32 * q] + b13v[q] + he[lane + 32 * q];
                ssum += v[q];
            }
#pragma unroll
            for (int off = 16; off > 0; off >>= 1) ssum += __shfl_xor_sync(0xffffffffu, ssum, off);
            float mean = ssum * (1.0f / H);
            float vs = 0.f;
#pragma unroll
            for (int q = 0; q < 4; q++) { v[q] -= mean; vs += v[q] * v[q]; }
#pragma unroll
            for (int off = 16; off > 0; off >>= 1) vs += __shfl_xor_sync(0xffffffffu, vs, off);
            float rs = rsqrtf(vs * (1.0f / H) + 1e-5f);
#pragma unroll
            for (int q = 0; q < 4; q++)
                outE[(size_t)(e0 + rr) * H + lane + 32 * q] = v[q] * rs * g3v[q] + be3v[q];
        }
    }
}

// ---------------- FFN (tensor): 32 nodes/CTA, grid 128 ----------------
__global__ void __launch_bounds__(256)
ffn_mma(const float* __restrict__ b_in, const float* __restrict__ b_out,
        const float* __restrict__ g2, const float* __restrict__ be2,
        const float* __restrict__ maskV, float* __restrict__ outV) {
    extern __shared__ float smf[];
    float* sXa = smf;
    float* sXb = smf + 4224;
    float* sW  = smf + 8448;
    const int tid = threadIdx.x;
    const int w = tid >> 5, lane = tid & 31;
    const int p0 = blockIdx.x * 32;

    {
        const int r = tid >> 3, c0 = (tid & 7) * 16;
        const float* a = g_hV1 + (size_t)(p0 + r) * H + c0;
        float* xa = sXa + r * XP + c0;
#pragma unroll
        for (int c = 0; c < 16; c += 4) {
            float4 v = *(const float4*)(a + c);
            xa[c] = to_tf32(v.x); xa[c+1] = to_tf32(v.y);
            xa[c+2] = to_tf32(v.z); xa[c+3] = to_tf32(v.w);
        }
    }

    float acc[2][2][4], acc2[2][2][4];
    zero_acc32(acc2);
#pragma unroll
    for (int nc = 0; nc < 4; nc++) {
        zero_acc32(acc);
        gemm32(sXa, sW, g_Wt + (W_INT + nc) * HH, tid, acc);
        __syncthreads();
        epi_bias_gelu32(sXb, tid, acc, b_in + nc * 128);
        gemm32(sXb, sW, g_Wt + (W_OUTT + nc) * HH, tid, acc2);
    }
    __syncthreads();
    store_acc32(sXb, tid, acc2);
    __syncthreads();

    for (int rr = w * 4; rr < w * 4 + 4; rr++) {
        const size_t row = p0 + rr;
        const float* res = g_hV1 + row * H;
        float u[4];
        float s = 0.f;
#pragma unroll
        for (int q = 0; q < 4; q++) {
            int c = lane + 32 * q;
            u[q] = sXb[rr * XP + c] + res[c] + b_out[c];
            s += u[q];
        }
#pragma unroll
        for (int off = 16; off > 0; off >>= 1) s += __shfl_xor_sync(0xffffffffu, s, off);
        float mean = s * (1.0f / H);
        float vs = 0.f;
#pragma unroll
        for (int q = 0; q < 4; q++) { u[q] -= mean; vs += u[q] * u[q]; }
#pragma unroll
        for (int off = 16; off > 0; off >>= 1) vs += __shfl_xor_sync(0xffffffffu, vs, off);
        float rs = rsqrtf(vs * (1.0f / H) + 1e-5f);
        float mv = maskV[row];
#pragma unroll
        for (int q = 0; q < 4; q++) {
            int c = lane + 32 * q;
            outV[row * H + c] = (u[q] * rs * g2[c] + be2[c]) * mv;
        }
    }
}

// ---------------- launch ----------------
extern "C" void kernel_launch(void* const* d_in, const int* in_sizes, int n_in,
                              void* d_out, int out_size) {
    const float* hV    = (const float*)d_in[0];
    const float* hVa   = (const float*)d_in[1];
    const float* hE    = (const float*)d_in[2];
    const float* W1    = (const float*)d_in[3];
    const float* b1    = (const float*)d_in[4];
    const float* W2    = (const float*)d_in[5];
    const float* b2    = (const float*)d_in[6];
    const float* W3    = (const float*)d_in[7];
    const float* b3    = (const float*)d_in[8];
    const float* W11   = (const float*)d_in[9];
    const float* b11   = (const float*)d_in[10];
    const float* W12   = (const float*)d_in[11];
    const float* b12   = (const float*)d_in[12];
    const float* W13   = (const float*)d_in[13];
    const float* b13   = (const float*)d_in[14];
    const float* W_in  = (const float*)d_in[15];
    const float* b_in  = (const float*)d_in[16];
    const float* W_out = (const float*)d_in[17];
    const float* b_out = (const float*)d_in[18];
    const float* g1    = (const float*)d_in[19];
    const float* be1   = (const float*)d_in[20];
    const float* g2    = (const float*)d_in[21];
    const float* be2   = (const float*)d_in[22];
    const float* g3    = (const float*)d_in[23];
    const float* be3   = (const float*)d_in[24];
    const float* maskV = (const float*)d_in[25];
    const float* maskA = (const float*)d_in[26];
    const int*   Eidx  = (const int*)d_in[27];

    const int BN = in_sizes[0] / H;   // 4096
    float* outV = (float*)d_out;
    float* outE = (float*)d_out + (size_t)BN * H;

    const size_t smemCH   = SMEM_CH * sizeof(float);          // 109.6 KB
    const size_t smemPRE1 = (33792 + 8704) * sizeof(float);   // 166 KB
    const size_t smemSML  = (16896 + 8704) * sizeof(float);   // 100 KB
    const size_t smemFFN  = 17152 * sizeof(float);            // 68.6 KB

    cudaFuncSetAttribute(node_mma_kernel, cudaFuncAttributeMaxDynamicSharedMemorySize, (int)smemCH);
    cudaFuncSetAttribute(edge_mma_kernel, cudaFuncAttributeMaxDynamicSharedMemorySize, (int)smemCH);
    cudaFuncSetAttribute(pre1_mma, cudaFuncAttributeMaxDynamicSharedMemorySize, (int)smemPRE1);
    cudaFuncSetAttribute(pre2_mma, cudaFuncAttributeMaxDynamicSharedMemorySize, (int)smemSML);
    cudaFuncSetAttribute(ffn_mma,  cudaFuncAttributeMaxDynamicSharedMemorySize, (int)smemFFN);

    prep_weights<<<(19 * HH + 255) / 256, 256>>>(W1, W2, W3, W11, W12, W13, W_in, W_out);
    pre1_mma<<<dim3(BN / 128, 2), 256, smemPRE1>>>(hV, hVa, b1);
    node_mma_kernel<<<BN / 4, 128, smemCH>>>(hV, hE, b2, b3, g1, be1, maskA, Eidx);
    ffn_mma<<<BN / 32, 256, smemFFN>>>(b_in, b_out, g2, be2, maskV, outV);
    pre2_mma<<<dim3(BN / 128, 2), 256, smemSML>>>(outV, b11);
    edge_mma_kernel<<<BN / 4, 128, smemCH>>>(hE, b12, b13, g3, be3, Eidx, outE);
}

// round 12
// speedup vs baseline: 1.0724x; 1.0724x over previous
#include <cuda_runtime.h>
#include <cstdint>
#include <math.h>

#define H      128
#define HH     (H * H)
#define KNB    48
#define NN     2048
#define BNTOT  4096
#define XP     132          // activation tile pitch (floats)
#define WP     68           // weight tile pitch (floats)

// weight matrix slots in g_Wt (all 128x128 [n][kperm], tf32-rounded)
#define W_E1   0
#define W_2T   1
#define W_3T   2
#define W_11E  3
#define W_12T  4
#define W_13T  5
#define W_1V   6
#define W_1G   7
#define W_1A   8
#define W_11V  9
#define W_11G  10
#define W_INT  11   // 11..14: W_in^T chunks
#define W_OUTT 15   // 15..18: W_out^T chunks

__device__ float g_Wt[19 * HH];
__device__ float g_D1[BNTOT * H];
__device__ float g_P1[BNTOT * H];
__device__ float g_D2[BNTOT * H];
__device__ float g_P2[BNTOT * H];
__device__ float g_hV1[BNTOT * H];

__device__ __forceinline__ float to_tf32(float x) {
    uint32_t u;
    asm("cvt.rna.tf32.f32 %0, %1;" : "=r"(u) : "f"(x));
    return __uint_as_float(u);
}

__device__ __forceinline__ float gelu_exact(float x) {
    return 0.5f * x * (1.0f + erff(x * 0.70710678118654752f));
}

__device__ __forceinline__ void mma_tf32(float d[4], const uint32_t a[4], const uint32_t b[2]) {
    asm volatile("mma.sync.aligned.m16n8k8.row.col.f32.tf32.tf32.f32 "
                 "{%0,%1,%2,%3}, {%4,%5,%6,%7}, {%8,%9}, {%0,%1,%2,%3};"
                 : "+f"(d[0]), "+f"(d[1]), "+f"(d[2]), "+f"(d[3])
                 : "r"(a[0]), "r"(a[1]), "r"(a[2]), "r"(a[3]), "r"(b[0]), "r"(b[1]));
}

// stage one 64-k half of a weight matrix (128n x 64k permuted floats) into sW
__device__ __forceinline__ void stage_W_half(float* __restrict__ sW,
                                             const float* __restrict__ Wg, int h, int tid) {
#pragma unroll
    for (int i = 0; i < 8; i++) {
        int idx = tid + 256 * i;
        int n = idx >> 4, q = idx & 15;
        float4 v = *(const float4*)(Wg + n * H + h * 64 + q * 4);
        *(float4*)(sW + n * WP + q * 4) = v;
    }
}

// ---------------- 128x128x128 tf32 GEMM, 256 threads (8 warps, 4m x 2n) ----------------
// B is k-pair-permuted: {W[n][k], W[n][k+4]} adjacent -> single float2 LDS.
__device__ __forceinline__ void gemm256(const float* __restrict__ sX, float* __restrict__ sW,
                                        const float* __restrict__ Wg, int tid,
                                        float acc[2][8][4]) {
    const int w = tid >> 5, lane = tid & 31;
    const int wm = w & 3, wn = w >> 2;
    const int lr = lane >> 2, lc = lane & 3;
    const float* sXw = sX + (wm * 32 + lr) * XP + lc;
    const float* sWb = sW + (wn * 64 + lr) * WP + 2 * lc;
#pragma unroll
    for (int h = 0; h < 2; h++) {
        __syncthreads();
        stage_W_half(sW, Wg, h, tid);
        __syncthreads();
#pragma unroll
        for (int k8 = 0; k8 < 8; k8++) {
            const int kl = k8 * 8;
            uint32_t a[2][4];
#pragma unroll
            for (int mt = 0; mt < 2; mt++) {
                const float* ap = sXw + mt * (16 * XP) + h * 64 + kl;
                a[mt][0] = __float_as_uint(ap[0]);
                a[mt][1] = __float_as_uint(ap[8 * XP]);
                a[mt][2] = __float_as_uint(ap[4]);
                a[mt][3] = __float_as_uint(ap[8 * XP + 4]);
            }
#pragma unroll
            for (int nt = 0; nt < 8; nt++) {
                float2 bv = *(const float2*)(sWb + nt * (8 * WP) + kl);
                uint32_t b[2] = {__float_as_uint(bv.x), __float_as_uint(bv.y)};
                mma_tf32(acc[0][nt], a[0], b);
                mma_tf32(acc[1][nt], a[1], b);
            }
        }
    }
}

// ---------------- 64x128x128 tf32 GEMM, 256 threads (4m x 2n, warp tile 16x64) ----------
__device__ __forceinline__ void gemm64(const float* __restrict__ sX, float* __restrict__ sW,
                                       const float* __restrict__ Wg, int tid,
                                       float acc[8][4]) {
    const int w = tid >> 5, lane = tid & 31;
    const int wm = w & 3, wn = w >> 2;
    const int lr = lane >> 2, lc = lane & 3;
    const float* sXw = sX + (wm * 16 + lr) * XP + lc;
    const float* sWb = sW + (wn * 64 + lr) * WP + 2 * lc;
#pragma unroll
    for (int h = 0; h < 2; h++) {
        __syncthreads();
        stage_W_half(sW, Wg, h, tid);
        __syncthreads();
#pragma unroll
        for (int k8 = 0; k8 < 8; k8++) {
            const int kl = k8 * 8;
            const float* ap = sXw + h * 64 + kl;
            uint32_t a[4];
            a[0] = __float_as_uint(ap[0]);
            a[1] = __float_as_uint(ap[8 * XP]);
            a[2] = __float_as_uint(ap[4]);
            a[3] = __float_as_uint(ap[8 * XP + 4]);
#pragma unroll
            for (int nt = 0; nt < 8; nt++) {
                float2 bv = *(const float2*)(sWb + nt * (8 * WP) + kl);
                uint32_t b[2] = {__float_as_uint(bv.x), __float_as_uint(bv.y)};
                mma_tf32(acc[nt], a, b);
            }
        }
    }
}

// ---------------- 32x128x128 tf32 GEMM, 256 threads (8 warps across n) ----------------
__device__ __forceinline__ void gemm32(const float* __restrict__ sX, float* __restrict__ sW,
                                       const float* __restrict__ Wg, int tid,
                                       float acc[2][2][4]) {
    const int w = tid >> 5, lane = tid & 31;
    const int lr = lane >> 2, lc = lane & 3;
    const float* sXw = sX + lr * XP + lc;
    const float* sWb = sW + (w * 16 + lr) * WP + 2 * lc;
#pragma unroll
    for (int h = 0; h < 2; h++) {
        __syncthreads();
        stage_W_half(sW, Wg, h, tid);
        __syncthreads();
#pragma unroll
        for (int k8 = 0; k8 < 8; k8++) {
            const int kl = k8 * 8;
            uint32_t a[2][4];
#pragma unroll
            for (int mt = 0; mt < 2; mt++) {
                const float* ap = sXw + mt * (16 * XP) + h * 64 + kl;
                a[mt][0] = __float_as_uint(ap[0]);
                a[mt][1] = __float_as_uint(ap[8 * XP]);
                a[mt][2] = __float_as_uint(ap[4]);
                a[mt][3] = __float_as_uint(ap[8 * XP + 4]);
            }
#pragma unroll
            for (int nt = 0; nt < 2; nt++) {
                float2 bv = *(const float2*)(sWb + nt * (8 * WP) + kl);
                uint32_t b[2] = {__float_as_uint(bv.x), __float_as_uint(bv.y)};
                mma_tf32(acc[0][nt], a[0], b);
                mma_tf32(acc[1][nt], a[1], b);
            }
        }
    }
}

__device__ __forceinline__ void zero_acc(float acc[2][8][4]) {
#pragma unroll
    for (int mt = 0; mt < 2; mt++)
#pragma unroll
        for (int nt = 0; nt < 8; nt++)
#pragma unroll
            for (int q = 0; q < 4; q++) acc[mt][nt][q] = 0.f;
}

__device__ __forceinline__ void zero_acc8(float acc[8][4]) {
#pragma unroll
    for (int nt = 0; nt < 8; nt++)
#pragma unroll
        for (int q = 0; q < 4; q++) acc[nt][q] = 0.f;
}

__device__ __forceinline__ void zero_acc32(float acc[2][2][4]) {
#pragma unroll
    for (int mt = 0; mt < 2; mt++)
#pragma unroll
        for (int nt = 0; nt < 2; nt++)
#pragma unroll
            for (int q = 0; q < 4; q++) acc[mt][nt][q] = 0.f;
}

// ---------------- 64-row epilogues (warp tile 16x64) ----------------
__device__ __forceinline__ void store_acc64(float* __restrict__ dst, int tid,
                                            const float acc[8][4]) {
    const int w = tid >> 5, lane = tid & 31;
    const int wm = w & 3, wn = w >> 2;
    const int lr = lane >> 2, lc = lane & 3;
    float* cx = dst + (wm * 16 + lr) * XP + wn * 64 + 2 * lc;
#pragma unroll
    for (int nt = 0; nt < 8; nt++) {
        *(float2*)(cx + nt * 8) = make_float2(acc[nt][0], acc[nt][1]);
        *(float2*)(cx + 8 * XP + nt * 8) = make_float2(acc[nt][2], acc[nt][3]);
    }
}

__device__ __forceinline__ void epi1_reg64(float* __restrict__ sX, int tid, int t64,
                                           const float acc[8][4],
                                           const float* __restrict__ Pbase,
                                           const int* __restrict__ sIdxT,
                                           const float* __restrict__ sD) {
    const int w = tid >> 5, lane = tid & 31;
    const int wm = w & 3, wn = w >> 2;
    const int lr = lane >> 2, lc = lane & 3;
    const int r0 = wm * 16 + lr, r1 = r0 + 8;
    const int src0 = sIdxT[r0], src1 = sIdxT[r1];
    const int nl0 = (t64 + r0) / KNB, nl1 = (t64 + r1) / KNB;
    const float* p0 = Pbase + (size_t)src0 * H;
    const float* p1 = Pbase + (size_t)src1 * H;
    const float* d0 = sD + nl0 * H;
    const float* d1 = sD + nl1 * H;
#pragma unroll
    for (int nt = 0; nt < 8; nt++) {
        int col = wn * 64 + nt * 8 + 2 * lc;
        float2 pa = *(const float2*)(p0 + col);
        float2 pb = *(const float2*)(p1 + col);
        float2 da = *(const float2*)(d0 + col);
        float2 db = *(const float2*)(d1 + col);
        *(float2*)(sX + r0 * XP + col) =
            make_float2(to_tf32(gelu_exact(acc[nt][0] + da.x + pa.x)),
                        to_tf32(gelu_exact(acc[nt][1] + da.y + pa.y)));
        *(float2*)(sX + r1 * XP + col) =
            make_float2(to_tf32(gelu_exact(acc[nt][2] + db.x + pb.x)),
                        to_tf32(gelu_exact(acc[nt][3] + db.y + pb.y)));
    }
}

__device__ __forceinline__ void epi_bias_gelu64(float* __restrict__ dst, int tid,
                                                const float acc[8][4],
                                                const float* __restrict__ bias) {
    const int w = tid >> 5, lane = tid & 31;
    const int wm = w & 3, wn = w >> 2;
    const int lr = lane >> 2, lc = lane & 3;
    float* cx = dst + (wm * 16 + lr) * XP + wn * 64 + 2 * lc;
#pragma unroll
    for (int nt = 0; nt < 8; nt++) {
        float2 bv = *(const float2*)(bias + wn * 64 + nt * 8 + 2 * lc);
        *(float2*)(cx + nt * 8) =
            make_float2(to_tf32(gelu_exact(acc[nt][0] + bv.x)),
                        to_tf32(gelu_exact(acc[nt][1] + bv.y)));
        *(float2*)(cx + 8 * XP + nt * 8) =
            make_float2(to_tf32(gelu_exact(acc[nt][2] + bv.x)),
                        to_tf32(gelu_exact(acc[nt][3] + bv.y)));
    }
}

__device__ __forceinline__ void epi_mask_bias64(float* __restrict__ dst, int tid,
                                                const float acc[8][4],
                                                const float* __restrict__ bias,
                                                const float* __restrict__ sMask) {
    const int w = tid >> 5, lane = tid & 31;
    const int wm = w & 3, wn = w >> 2;
    const int lr = lane >> 2, lc = lane & 3;
    const int r0 = wm * 16 + lr, r1 = r0 + 8;
    float mk0 = sMask[r0], mk1 = sMask[r1];
    float* cx = dst + r0 * XP + wn * 64 + 2 * lc;
#pragma unroll
    for (int nt = 0; nt < 8; nt++) {
        float2 bv = *(const float2*)(bias + wn * 64 + nt * 8 + 2 * lc);
        *(float2*)(cx + nt * 8) =
            make_float2(mk0 * (acc[nt][0] + bv.x), mk0 * (acc[nt][1] + bv.y));
        *(float2*)(cx + 8 * XP + nt * 8) =
            make_float2(mk1 * (acc[nt][2] + bv.x), mk1 * (acc[nt][3] + bv.y));
    }
}

// ---------------- 128-row epilogues (pre kernels) ----------------
__device__ __forceinline__ void epi_to_global(float* __restrict__ gdst, int p0, int tid,
                                              const float acc[2][8][4],
                                              const float* __restrict__ bias) {
    const int w = tid >> 5, lane = tid & 31;
    const int wm = w & 3, wn = w >> 2;
    const int lr = lane >> 2, lc = lane & 3;
#pragma unroll
    for (int nt = 0; nt < 8; nt++) {
        int col = wn * 64 + nt * 8 + 2 * lc;
        float2 bv = bias ? *(const float2*)(bias + col) : make_float2(0.f, 0.f);
#pragma unroll
        for (int mt = 0; mt < 2; mt++) {
            int r0 = wm * 32 + mt * 16 + lr;
            *(float2*)(gdst + (size_t)(p0 + r0) * H + col) =
                make_float2(acc[mt][nt][0] + bv.x, acc[mt][nt][1] + bv.y);
            *(float2*)(gdst + (size_t)(p0 + r0 + 8) * H + col) =
                make_float2(acc[mt][nt][2] + bv.x, acc[mt][nt][3] + bv.y);
        }
    }
}

__device__ __forceinline__ void epi_bias_gelu32(float* __restrict__ dst, int tid,
                                                const float acc[2][2][4],
                                                const float* __restrict__ bias) {
    const int w = tid >> 5, lane = tid & 31;
    const int lr = lane >> 2, lc = lane & 3;
    float* cx = dst + lr * XP + w * 16 + 2 * lc;
#pragma unroll
    for (int nt = 0; nt < 2; nt++) {
        float2 bv = *(const float2*)(bias + w * 16 + nt * 8 + 2 * lc);
#pragma unroll
        for (int mt = 0; mt < 2; mt++) {
            *(float2*)(cx + mt * (16 * XP) + nt * 8) =
                make_float2(to_tf32(gelu_exact(acc[mt][nt][0] + bv.x)),
                            to_tf32(gelu_exact(acc[mt][nt][1] + bv.y)));
            *(float2*)(cx + mt * (16 * XP) + 8 * XP + nt * 8) =
                make_float2(to_tf32(gelu_exact(acc[mt][nt][2] + bv.x)),
                            to_tf32(gelu_exact(acc[mt][nt][3] + bv.y)));
        }
    }
}

__device__ __forceinline__ void store_acc32(float* __restrict__ dst, int tid,
                                            const float acc[2][2][4]) {
    const int w = tid >> 5, lane = tid & 31;
    const int lr = lane >> 2, lc = lane & 3;
    float* cx = dst + lr * XP + w * 16 + 2 * lc;
#pragma unroll
    for (int mt = 0; mt < 2; mt++)
#pragma unroll
        for (int nt = 0; nt < 2; nt++) {
            *(float2*)(cx + mt * (16 * XP) + nt * 8) =
                make_float2(acc[mt][nt][0], acc[mt][nt][1]);
            *(float2*)(cx + mt * (16 * XP) + 8 * XP + nt * 8) =
                make_float2(acc[mt][nt][2], acc[mt][nt][3]);
        }
}

// ---------------- prep weights: transpose/fold + tf32 + k-pair permutation ----------------
__global__ void prep_weights(const float* __restrict__ W1, const float* __restrict__ W2,
                             const float* __restrict__ W3, const float* __restrict__ W11,
                             const float* __restrict__ W12, const float* __restrict__ W13,
                             const float* __restrict__ W_in, const float* __restrict__ W_out) {
    int idx = blockIdx.x * 256 + threadIdx.x;
    if (idx >= 19 * HH) return;
    int m = idx / HH;
    int r = (idx >> 7) & 127;
    int c = idx & 127;
    float v;
    switch (m) {
        case W_E1:  v = W1[(128 + c) * H + r] + W1[(384 + c) * H + r]; break;
        case W_2T:  v = W2[c * H + r]; break;
        case W_3T:  v = W3[c * H + r]; break;
        case W_11E: v = W11[(128 + c) * H + r]; break;
        case W_12T: v = W12[c * H + r]; break;
        case W_13T: v = W13[c * H + r]; break;
        case W_1V:  v = W1[c * H + r]; break;
        case W_1G:  v = W1[(256 + c) * H + r]; break;
        case W_1A:  v = W1[(512 + c) * H + r]; break;
        case W_11V: v = W11[c * H + r]; break;
        case W_11G: v = W11[(256 + c) * H + r]; break;
        default:
            if (m < W_OUTT) {
                int nc = m - W_INT;
                v = W_in[c * 512 + nc * 128 + r];
            } else {
                int kc = m - W_OUTT;
                v = W_out[(kc * 128 + c) * H + r];
            }
            break;
    }
    int kperm = (c & ~7) | ((c & 3) << 1) | ((c >> 2) & 1);
    g_Wt[m * HH + r * H + kperm] = to_tf32(v);
}

// ---------------- pre1 (grid 32x2) ----------------
__global__ void __launch_bounds__(256)
pre1_mma(const float* __restrict__ hV, const float* __restrict__ hVa,
         const float* __restrict__ b1) {
    extern __shared__ float smf[];
    float* sXa = smf;
    float* sXb = smf + 16896;
    float* sW  = smf + 33792;
    const int tid = threadIdx.x;
    const int p0 = blockIdx.x * 128;
    const int z = blockIdx.y;
    const int r = tid >> 1, ch = (tid & 1) * 64;

    {
        const float* a = hV + (size_t)(p0 + r) * H + ch;
        float* xa = sXa + r * XP + ch;
#pragma unroll
        for (int c = 0; c < 64; c += 4) {
            float4 v = *(const float4*)(a + c);
            xa[c] = to_tf32(v.x); xa[c+1] = to_tf32(v.y); xa[c+2] = to_tf32(v.z); xa[c+3] = to_tf32(v.w);
        }
        if (z == 1) {
            const float* b = hVa + (size_t)(p0 + r) * H + ch;
            float* xb = sXb + r * XP + ch;
#pragma unroll
            for (int c = 0; c < 64; c += 4) {
                float4 u = *(const float4*)(b + c);
                xb[c] = to_tf32(u.x); xb[c+1] = to_tf32(u.y); xb[c+2] = to_tf32(u.z); xb[c+3] = to_tf32(u.w);
            }
        }
    }

    float acc[2][8][4];
    zero_acc(acc);
    if (z == 0) {
        gemm256(sXa, sW, g_Wt + W_1V * HH, tid, acc);
        epi_to_global(g_D1, p0, tid, acc, b1);
    } else {
        gemm256(sXa, sW, g_Wt + W_1G * HH, tid, acc);
        gemm256(sXb, sW, g_Wt + W_1A * HH, tid, acc);
        epi_to_global(g_P1, p0, tid, acc, (const float*)nullptr);
    }
}

// ---------------- pre2 (grid 32x2) ----------------
__global__ void __launch_bounds__(256)
pre2_mma(const float* __restrict__ hVf, const float* __restrict__ b11) {
    extern __shared__ float smf[];
    float* sXa = smf;
    float* sW  = smf + 16896;
    const int tid = threadIdx.x;
    const int p0 = blockIdx.x * 128;
    const int z = blockIdx.y;
    const int r = tid >> 1, ch = (tid & 1) * 64;

    {
        const float* a = hVf + (size_t)(p0 + r) * H + ch;
        float* xa = sXa + r * XP + ch;
#pragma unroll
        for (int c = 0; c < 64; c += 4) {
            float4 v = *(const float4*)(a + c);
            xa[c] = to_tf32(v.x); xa[c+1] = to_tf32(v.y); xa[c+2] = to_tf32(v.z); xa[c+3] = to_tf32(v.w);
        }
    }

    float acc[2][8][4];
    zero_acc(acc);
    if (z == 0) {
        gemm256(sXa, sW, g_Wt + W_11V * HH, tid, acc);
        epi_to_global(g_D2, p0, tid, acc, b11);
    } else {
        gemm256(sXa, sW, g_Wt + W_11G * HH, tid, acc);
        epi_to_global(g_P2, p0, tid, acc, (const float*)nullptr);
    }
}

// node/edge smem layout (floats): sX 0..8448 | sW 8448..17152 (alias sAcc2 1024) |
//   sD 17152..17664 | sAcc 17664..18176 | sIdx 18176..18368 (int) |
//   sMask 18368..18432 | sRed 18432..18448
#define SMEM_MLP 18448

// ---------------- node message MLP + sum_K + LN1 (4 nodes/CTA, 64-row tiles) ----------------
__global__ void __launch_bounds__(256, 3)
node_mma_kernel(const float* __restrict__ hV, const float* __restrict__ hE,
                const float* __restrict__ b2, const float* __restrict__ b3,
                const float* __restrict__ g1, const float* __restrict__ be1,
                const float* __restrict__ maskA, const int* __restrict__ Eidx) {
    extern __shared__ float smf[];
    float* sX    = smf;
    float* sW    = smf + 8448;
    float* sAcc2 = sW;
    float* sD    = smf + 17152;
    float* sAcc  = smf + 17664;
    int*   sIdx  = (int*)(smf + 18176);
    float* sMask = smf + 18368;
    float* sRed  = smf + 18432;

    const int tid = threadIdx.x;
    const int P0 = blockIdx.x * 4;
    const int bb = P0 >> 11;
    const float* P1b = g_P1 + (size_t)bb * NN * H;

    for (int i = tid; i < 4 * H; i += 256) {
        sD[i] = g_D1[(size_t)P0 * H + i];
        sAcc[i] = 0.f;
    }
    for (int i = tid; i < 4 * KNB; i += 256) sIdx[i] = Eidx[(size_t)P0 * KNB + i];

    float acc[8][4];

    for (int t = 0; t < 3; t++) {
        const int e0 = P0 * KNB + t * 64;

        __syncthreads();
        {
            int rr = tid >> 2, c0 = (tid & 3) * 32;
            const float* a = hE + (size_t)(e0 + rr) * H + c0;
            float* x = sX + rr * XP + c0;
#pragma unroll
            for (int c = 0; c < 32; c += 4) {
                float4 v = *(const float4*)(a + c);
                x[c] = to_tf32(v.x); x[c+1] = to_tf32(v.y);
                x[c+2] = to_tf32(v.z); x[c+3] = to_tf32(v.w);
            }
            if (tid < 64) sMask[tid] = maskA[e0 + tid];
        }

        // GEMM1 + register epi1
        zero_acc8(acc);
        gemm64(sX, sW, g_Wt + W_E1 * HH, tid, acc);
        __syncthreads();
        epi1_reg64(sX, tid, t * 64, acc, P1b, sIdx + t * 64, sD);

        // GEMM2 + register epi2
        zero_acc8(acc);
        gemm64(sX, sW, g_Wt + W_2T * HH, tid, acc);
        __syncthreads();
        epi_bias_gelu64(sX, tid, acc, b2);

        // GEMM3 + register epi3 (mask)
        zero_acc8(acc);
        gemm64(sX, sW, g_Wt + W_3T * HH, tid, acc);
        __syncthreads();
        epi_mask_bias64(sX, tid, acc, b3, sMask);
        for (int i = tid; i < 1024; i += 256) sAcc2[i] = 0.f;
        __syncthreads();

        // segment-sum rows -> per-node partials (2 halves of 32 rows)
        {
            const int col = tid & 127, half = tid >> 7;
            int rr = half * 32;
            int nl = (t * 64 + rr) / KNB;
            int nxt = (nl + 1) * KNB - t * 64;
            float a = 0.f;
            for (; rr < half * 32 + 32; rr++) {
                if (rr == nxt) { sAcc2[half * 512 + nl * 128 + col] = a; nl++; nxt += KNB; a = 0.f; }
                a += sX[rr * XP + col];
            }
            sAcc2[half * 512 + nl * 128 + col] = a;
        }
        __syncthreads();
        for (int i = tid; i < 512; i += 256)
            sAcc[i] += sAcc2[i] + sAcc2[512 + i];
    }
    __syncthreads();

    // LN1: 2 nodes at a time (2 steps)
    for (int step = 0; step < 2; step++) {
        const int g = tid >> 7;
        const int n = step * 2 + g;
        const int c = tid & 127;
        float u = hV[(size_t)(P0 + n) * H + c] + sAcc[n * 128 + c] * (1.0f / 30.0f);
        float s = u;
#pragma unroll
        for (int off = 16; off > 0; off >>= 1) s += __shfl_xor_sync(0xffffffffu, s, off);
        if ((tid & 31) == 0) sRed[tid >> 5] = s;
        __syncthreads();
        float mean = (sRed[g*4] + sRed[g*4+1] + sRed[g*4+2] + sRed[g*4+3]) * (1.0f / H);
        float d = u - mean;
        float v2 = d * d;
#pragma unroll
        for (int off = 16; off > 0; off >>= 1) v2 += __shfl_xor_sync(0xffffffffu, v2, off);
        if ((tid & 31) == 0) sRed[8 + (tid >> 5)] = v2;
        __syncthreads();
        float var = (sRed[8+g*4] + sRed[8+g*4+1] + sRed[8+g*4+2] + sRed[8+g*4+3]) * (1.0f / H);
        g_hV1[(size_t)(P0 + n) * H + c] = d * rsqrtf(var + 1e-5f) * g1[c] + be1[c];
        __syncthreads();
    }
}

// ---------------- edge update MLP + LN3 (4 nodes/CTA, 64-row tiles) ----------------
__global__ void __launch_bounds__(256, 3)
edge_mma_kernel(const float* __restrict__ hE,
                const float* __restrict__ b12, const float* __restrict__ b13,
                const float* __restrict__ g3, const float* __restrict__ be3,
                const int* __restrict__ Eidx, float* __restrict__ outE) {
    extern __shared__ float smf[];
    float* sX   = smf;
    float* sW   = smf + 8448;
    float* sD   = smf + 17152;
    int*   sIdx = (int*)(smf + 18176);

    const int tid = threadIdx.x;
    const int w = tid >> 5, lane = tid & 31;
    const int P0 = blockIdx.x * 4;
    const int bb = P0 >> 11;
    const float* P2b = g_P2 + (size_t)bb * NN * H;

    for (int i = tid; i < 4 * H; i += 256) sD[i] = g_D2[(size_t)P0 * H + i];
    for (int i = tid; i < 4 * KNB; i += 256) sIdx[i] = Eidx[(size_t)P0 * KNB + i];

    float b13v[4], g3v[4], be3v[4];
#pragma unroll
    for (int q = 0; q < 4; q++) {
        b13v[q] = b13[lane + 32 * q];
        g3v[q]  = g3[lane + 32 * q];
        be3v[q] = be3[lane + 32 * q];
    }

    float acc[8][4];

    for (int t = 0; t < 3; t++) {
        const int e0 = P0 * KNB + t * 64;

        __syncthreads();
        {
            int rr = tid >> 2, c0 = (tid & 3) * 32;
            const float* a = hE + (size_t)(e0 + rr) * H + c0;
            float* x = sX + rr * XP + c0;
#pragma unroll
            for (int c = 0; c < 32; c += 4) {
                float4 v = *(const float4*)(a + c);
                x[c] = to_tf32(v.x); x[c+1] = to_tf32(v.y);
                x[c+2] = to_tf32(v.z); x[c+3] = to_tf32(v.w);
            }
        }

        zero_acc8(acc);
        gemm64(sX, sW, g_Wt + W_11E * HH, tid, acc);
        __syncthreads();
        epi1_reg64(sX, tid, t * 64, acc, P2b, sIdx + t * 64, sD);

        zero_acc8(acc);
        gemm64(sX, sW, g_Wt + W_12T * HH, tid, acc);
        __syncthreads();
        epi_bias_gelu64(sX, tid, acc, b12);

        zero_acc8(acc);
        gemm64(sX, sW, g_Wt + W_13T * HH, tid, acc);
        __syncthreads();
        store_acc64(sX, tid, acc);
        __syncthreads();

        // LN3 with fused b13 + hE residual: each warp 8 rows
        for (int rr = w * 8; rr < w * 8 + 8; rr++) {
            const float* he = hE + (size_t)(e0 + rr) * H;
            float v[4];
            float ssum = 0.f;
#pragma unroll
            for (int q = 0; q < 4; q++) {
                v[q] = sX[rr * XP + lane + 32 * q] + b13v[q] + he[lane + 32 * q];
                ssum += v[q];
            }
#pragma unroll
            for (int off = 16; off > 0; off >>= 1) ssum += __shfl_xor_sync(0xffffffffu, ssum, off);
            float mean = ssum * (1.0f / H);
            float vs = 0.f;
#pragma unroll
            for (int q = 0; q < 4; q++) { v[q] -= mean; vs += v[q] * v[q]; }
#pragma unroll
            for (int off = 16; off > 0; off >>= 1) vs += __shfl_xor_sync(0xffffffffu, vs, off);
            float rs = rsqrtf(vs * (1.0f / H) + 1e-5f);
#pragma unroll
            for (int q = 0; q < 4; q++)
                outE[(size_t)(e0 + rr) * H + lane + 32 * q] = v[q] * rs * g3v[q] + be3v[q];
        }
    }
}

// ---------------- FFN (tensor): 32 nodes/CTA, grid 128 ----------------
// smem: sXa 32*132=4224 | sXb 4224 | sW 8704 -> 17152 floats (~68.6KB)
__global__ void __launch_bounds__(256)
ffn_mma(const float* __restrict__ b_in, const float* __restrict__ b_out,
        const float* __restrict__ g2, const float* __restrict__ be2,
        const float* __restrict__ maskV, float* __restrict__ outV) {
    extern __shared__ float smf[];
    float* sXa = smf;
    float* sXb = smf + 4224;
    float* sW  = smf + 8448;
    const int tid = threadIdx.x;
    const int w = tid >> 5, lane = tid & 31;
    const int p0 = blockIdx.x * 32;

    {
        const int r = tid >> 3, c0 = (tid & 7) * 16;
        const float* a = g_hV1 + (size_t)(p0 + r) * H + c0;
        float* xa = sXa + r * XP + c0;
#pragma unroll
        for (int c = 0; c < 16; c += 4) {
            float4 v = *(const float4*)(a + c);
            xa[c] = to_tf32(v.x); xa[c+1] = to_tf32(v.y);
            xa[c+2] = to_tf32(v.z); xa[c+3] = to_tf32(v.w);
        }
    }

    float acc[2][2][4], acc2[2][2][4];
    zero_acc32(acc2);
#pragma unroll
    for (int nc = 0; nc < 4; nc++) {
        zero_acc32(acc);
        gemm32(sXa, sW, g_Wt + (W_INT + nc) * HH, tid, acc);
        __syncthreads();
        epi_bias_gelu32(sXb, tid, acc, b_in + nc * 128);
        gemm32(sXb, sW, g_Wt + (W_OUTT + nc) * HH, tid, acc2);
    }
    __syncthreads();
    store_acc32(sXb, tid, acc2);
    __syncthreads();

    for (int rr = w * 4; rr < w * 4 + 4; rr++) {
        const size_t row = p0 + rr;
        const float* res = g_hV1 + row * H;
        float u[4];
        float s = 0.f;
#pragma unroll
        for (int q = 0; q < 4; q++) {
            int c = lane + 32 * q;
            u[q] = sXb[rr * XP + c] + res[c] + b_out[c];
            s += u[q];
        }
#pragma unroll
        for (int off = 16; off > 0; off >>= 1) s += __shfl_xor_sync(0xffffffffu, s, off);
        float mean = s * (1.0f / H);
        float vs = 0.f;
#pragma unroll
        for (int q = 0; q < 4; q++) { u[q] -= mean; vs += u[q] * u[q]; }
#pragma unroll
        for (int off = 16; off > 0; off >>= 1) vs += __shfl_xor_sync(0xffffffffu, vs, off);
        float rs = rsqrtf(vs * (1.0f / H) + 1e-5f);
        float mv = maskV[row];
#pragma unroll
        for (int q = 0; q < 4; q++) {
            int c = lane + 32 * q;
            outV[row * H + c] = (u[q] * rs * g2[c] + be2[c]) * mv;
        }
    }
}

// ---------------- launch ----------------
extern "C" void kernel_launch(void* const* d_in, const int* in_sizes, int n_in,
                              void* d_out, int out_size) {
    const float* hV    = (const float*)d_in[0];
    const float* hVa   = (const float*)d_in[1];
    const float* hE    = (const float*)d_in[2];
    const float* W1    = (const float*)d_in[3];
    const float* b1    = (const float*)d_in[4];
    const float* W2    = (const float*)d_in[5];
    const float* b2    = (const float*)d_in[6];
    const float* W3    = (const float*)d_in[7];
    const float* b3    = (const float*)d_in[8];
    const float* W11   = (const float*)d_in[9];
    const float* b11   = (const float*)d_in[10];
    const float* W12   = (const float*)d_in[11];
    const float* b12   = (const float*)d_in[12];
    const float* W13   = (const float*)d_in[13];
    const float* b13   = (const float*)d_in[14];
    const float* W_in  = (const float*)d_in[15];
    const float* b_in  = (const float*)d_in[16];
    const float* W_out = (const float*)d_in[17];
    const float* b_out = (const float*)d_in[18];
    const float* g1    = (const float*)d_in[19];
    const float* be1   = (const float*)d_in[20];
    const float* g2    = (const float*)d_in[21];
    const float* be2   = (const float*)d_in[22];
    const float* g3    = (const float*)d_in[23];
    const float* be3   = (const float*)d_in[24];
    const float* maskV = (const float*)d_in[25];
    const float* maskA = (const float*)d_in[26];
    const int*   Eidx  = (const int*)d_in[27];

    const int BN = in_sizes[0] / H;   // 4096
    float* outV = (float*)d_out;
    float* outE = (float*)d_out + (size_t)BN * H;

    const size_t smemMLP  = SMEM_MLP * sizeof(float);         // ~73.8 KB (3 CTAs/SM)
    const size_t smemPRE1 = (33792 + 8704) * sizeof(float);   // 166 KB
    const size_t smemSML  = (16896 + 8704) * sizeof(float);   // 100 KB
    const size_t smemFFN  = 17152 * sizeof(float);            // 68.6 KB

    cudaFuncSetAttribute(node_mma_kernel, cudaFuncAttributeMaxDynamicSharedMemorySize, (int)smemMLP);
    cudaFuncSetAttribute(edge_mma_kernel, cudaFuncAttributeMaxDynamicSharedMemorySize, (int)smemMLP);
    cudaFuncSetAttribute(pre1_mma, cudaFuncAttributeMaxDynamicSharedMemorySize, (int)smemPRE1);
    cudaFuncSetAttribute(pre2_mma, cudaFuncAttributeMaxDynamicSharedMemorySize, (int)smemSML);
    cudaFuncSetAttribute(ffn_mma,  cudaFuncAttributeMaxDynamicSharedMemorySize, (int)smemFFN);

    prep_weights<<<(19 * HH + 255) / 256, 256>>>(W1, W2, W3, W11, W12, W13, W_in, W_out);
    pre1_mma<<<dim3(BN / 128, 2), 256, smemPRE1>>>(hV, hVa, b1);
    node_mma_kernel<<<BN / 4, 256, smemMLP>>>(hV, hE, b2, b3, g1, be1, maskA, Eidx);
    ffn_mma<<<BN / 32, 256, smemFFN>>>(b_in, b_out, g2, be2, maskV, outV);
    pre2_mma<<<dim3(BN / 128, 2), 256, smemSML>>>(outV, b11);
    edge_mma_kernel<<<BN / 4, 256, smemMLP>>>(hE, b12, b13, g3, be3, Eidx, outE);
}

// round 14
// speedup vs baseline: 1.2337x; 1.1504x over previous
#include <cuda_runtime.h>
#include <cstdint>
#include <math.h>

#define H      128
#define HH     (H * H)
#define KNB    48
#define NN     2048
#define BNTOT  4096
#define XP     132          // activation tile pitch (floats)
#define WP     68           // weight tile pitch (floats)

// weight matrix slots in g_Wt (all 128x128 [n][kperm], tf32-rounded)
#define W_E1   0
#define W_2T   1
#define W_3T   2
#define W_11E  3
#define W_12T  4
#define W_13T  5
#define W_1V   6
#define W_1G   7
#define W_1A   8
#define W_11V  9
#define W_11G  10
#define W_INT  11   // 11..14: W_in^T chunks
#define W_OUTT 15   // 15..18: W_out^T chunks

__device__ float g_Wt[19 * HH];
__device__ float g_D1[BNTOT * H];
__device__ float g_P1[BNTOT * H];
__device__ float g_D2[BNTOT * H];
__device__ float g_P2[BNTOT * H];
__device__ float g_hV1[BNTOT * H];

__device__ __forceinline__ float to_tf32(float x) {
    uint32_t u;
    asm("cvt.rna.tf32.f32 %0, %1;" : "=r"(u) : "f"(x));
    return __uint_as_float(u);
}

__device__ __forceinline__ float gelu_exact(float x) {
    return 0.5f * x * (1.0f + erff(x * 0.70710678118654752f));
}

__device__ __forceinline__ void mma_tf32(float d[4], const uint32_t a[4], const uint32_t b[2]) {
    asm volatile("mma.sync.aligned.m16n8k8.row.col.f32.tf32.tf32.f32 "
                 "{%0,%1,%2,%3}, {%4,%5,%6,%7}, {%8,%9}, {%0,%1,%2,%3};"
                 : "+f"(d[0]), "+f"(d[1]), "+f"(d[2]), "+f"(d[3])
                 : "r"(a[0]), "r"(a[1]), "r"(a[2]), "r"(a[3]), "r"(b[0]), "r"(b[1]));
}

// stage one 64-k half of a weight matrix (128n x 64k permuted floats) into sW
__device__ __forceinline__ void stage_W_half(float* __restrict__ sW,
                                             const float* __restrict__ Wg, int h, int tid) {
#pragma unroll
    for (int i = 0; i < 8; i++) {
        int idx = tid + 256 * i;
        int n = idx >> 4, q = idx & 15;
        float4 v = *(const float4*)(Wg + n * H + h * 64 + q * 4);
        *(float4*)(sW + n * WP + q * 4) = v;
    }
}

// ---------------- 128x128x128 tf32 GEMM, 256 threads (8 warps, 4m x 2n) ----------------
// B is k-pair-permuted: {W[n][k], W[n][k+4]} adjacent -> single float2 LDS.
__device__ __forceinline__ void gemm256(const float* __restrict__ sX, float* __restrict__ sW,
                                        const float* __restrict__ Wg, int tid,
                                        float acc[2][8][4]) {
    const int w = tid >> 5, lane = tid & 31;
    const int wm = w & 3, wn = w >> 2;
    const int lr = lane >> 2, lc = lane & 3;
    const float* sXw = sX + (wm * 32 + lr) * XP + lc;
    const float* sWb = sW + (wn * 64 + lr) * WP + 2 * lc;
#pragma unroll
    for (int h = 0; h < 2; h++) {
        __syncthreads();
        stage_W_half(sW, Wg, h, tid);
        __syncthreads();
#pragma unroll
        for (int k8 = 0; k8 < 8; k8++) {
            const int kl = k8 * 8;
            uint32_t a[2][4];
#pragma unroll
            for (int mt = 0; mt < 2; mt++) {
                const float* ap = sXw + mt * (16 * XP) + h * 64 + kl;
                a[mt][0] = __float_as_uint(ap[0]);
                a[mt][1] = __float_as_uint(ap[8 * XP]);
                a[mt][2] = __float_as_uint(ap[4]);
                a[mt][3] = __float_as_uint(ap[8 * XP + 4]);
            }
#pragma unroll
            for (int nt = 0; nt < 8; nt++) {
                float2 bv = *(const float2*)(sWb + nt * (8 * WP) + kl);
                uint32_t b[2] = {__float_as_uint(bv.x), __float_as_uint(bv.y)};
                mma_tf32(acc[0][nt], a[0], b);
                mma_tf32(acc[1][nt], a[1], b);
            }
        }
    }
}

// ---------------- 64x128x128 tf32 GEMM, 256 threads (4m x 2n, warp tile 16x64) ----------
__device__ __forceinline__ void gemm64(const float* __restrict__ sX, float* __restrict__ sW,
                                       const float* __restrict__ Wg, int tid,
                                       float acc[8][4]) {
    const int w = tid >> 5, lane = tid & 31;
    const int wm = w & 3, wn = w >> 2;
    const int lr = lane >> 2, lc = lane & 3;
    const float* sXw = sX + (wm * 16 + lr) * XP + lc;
    const float* sWb = sW + (wn * 64 + lr) * WP + 2 * lc;
#pragma unroll
    for (int h = 0; h < 2; h++) {
        __syncthreads();
        stage_W_half(sW, Wg, h, tid);
        __syncthreads();
#pragma unroll
        for (int k8 = 0; k8 < 8; k8++) {
            const int kl = k8 * 8;
            const float* ap = sXw + h * 64 + kl;
            uint32_t a[4];
            a[0] = __float_as_uint(ap[0]);
            a[1] = __float_as_uint(ap[8 * XP]);
            a[2] = __float_as_uint(ap[4]);
            a[3] = __float_as_uint(ap[8 * XP + 4]);
#pragma unroll
            for (int nt = 0; nt < 8; nt++) {
                float2 bv = *(const float2*)(sWb + nt * (8 * WP) + kl);
                uint32_t b[2] = {__float_as_uint(bv.x), __float_as_uint(bv.y)};
                mma_tf32(acc[nt], a, b);
            }
        }
    }
}

// ---------------- 32x128x128 tf32 GEMM, 256 threads (8 warps across n) ----------------
__device__ __forceinline__ void gemm32(const float* __restrict__ sX, float* __restrict__ sW,
                                       const float* __restrict__ Wg, int tid,
                                       float acc[2][2][4]) {
    const int w = tid >> 5, lane = tid & 31;
    const int lr = lane >> 2, lc = lane & 3;
    const float* sXw = sX + lr * XP + lc;
    const float* sWb = sW + (w * 16 + lr) * WP + 2 * lc;
#pragma unroll
    for (int h = 0; h < 2; h++) {
        __syncthreads();
        stage_W_half(sW, Wg, h, tid);
        __syncthreads();
#pragma unroll
        for (int k8 = 0; k8 < 8; k8++) {
            const int kl = k8 * 8;
            uint32_t a[2][4];
#pragma unroll
            for (int mt = 0; mt < 2; mt++) {
                const float* ap = sXw + mt * (16 * XP) + h * 64 + kl;
                a[mt][0] = __float_as_uint(ap[0]);
                a[mt][1] = __float_as_uint(ap[8 * XP]);
                a[mt][2] = __float_as_uint(ap[4]);
                a[mt][3] = __float_as_uint(ap[8 * XP + 4]);
            }
#pragma unroll
            for (int nt = 0; nt < 2; nt++) {
                float2 bv = *(const float2*)(sWb + nt * (8 * WP) + kl);
                uint32_t b[2] = {__float_as_uint(bv.x), __float_as_uint(bv.y)};
                mma_tf32(acc[0][nt], a[0], b);
                mma_tf32(acc[1][nt], a[1], b);
            }
        }
    }
}

__device__ __forceinline__ void zero_acc(float acc[2][8][4]) {
#pragma unroll
    for (int mt = 0; mt < 2; mt++)
#pragma unroll
        for (int nt = 0; nt < 8; nt++)
#pragma unroll
            for (int q = 0; q < 4; q++) acc[mt][nt][q] = 0.f;
}

__device__ __forceinline__ void zero_acc8(float acc[8][4]) {
#pragma unroll
    for (int nt = 0; nt < 8; nt++)
#pragma unroll
        for (int q = 0; q < 4; q++) acc[nt][q] = 0.f;
}

__device__ __forceinline__ void zero_acc32(float acc[2][2][4]) {
#pragma unroll
    for (int mt = 0; mt < 2; mt++)
#pragma unroll
        for (int nt = 0; nt < 2; nt++)
#pragma unroll
            for (int q = 0; q < 4; q++) acc[mt][nt][q] = 0.f;
}

__device__ __forceinline__ void store_acc(float* __restrict__ dst, int tid,
                                          const float acc[2][8][4]) {
    const int w = tid >> 5, lane = tid & 31;
    const int wm = w & 3, wn = w >> 2;
    const int lr = lane >> 2, lc = lane & 3;
    float* cx = dst + (wm * 32 + lr) * XP + wn * 64 + 2 * lc;
#pragma unroll
    for (int mt = 0; mt < 2; mt++)
#pragma unroll
        for (int nt = 0; nt < 8; nt++) {
            *(float2*)(cx + mt * (16 * XP) + nt * 8) =
                make_float2(acc[mt][nt][0], acc[mt][nt][1]);
            *(float2*)(cx + mt * (16 * XP) + 8 * XP + nt * 8) =
                make_float2(acc[mt][nt][2], acc[mt][nt][3]);
        }
}

// register epi1: sX = to_tf32(gelu(acc + sD[node(row)] + P[src(row)]))
__device__ __forceinline__ void epi1_reg(float* __restrict__ sX, int tid, int t128,
                                         const float acc[2][8][4],
                                         const float* __restrict__ Pbase,
                                         const int* __restrict__ sIdxT,
                                         const float* __restrict__ sD) {
    const int w = tid >> 5, lane = tid & 31;
    const int wm = w & 3, wn = w >> 2;
    const int lr = lane >> 2, lc = lane & 3;
#pragma unroll
    for (int mt = 0; mt < 2; mt++) {
#pragma unroll
        for (int hf = 0; hf < 2; hf++) {
            int r = wm * 32 + mt * 16 + lr + hf * 8;
            int src = sIdxT[r];
            int nl = (t128 + r) / KNB;
            const float* pr = Pbase + (size_t)src * H;
            const float* dn = sD + nl * H;
            float* xrow = sX + r * XP;
            const int ai = hf * 2;
#pragma unroll
            for (int nt = 0; nt < 8; nt++) {
                int col = wn * 64 + nt * 8 + 2 * lc;
                float2 p = *(const float2*)(pr + col);
                float2 d = *(const float2*)(dn + col);
                *(float2*)(xrow + col) =
                    make_float2(to_tf32(gelu_exact(acc[mt][nt][ai] + d.x + p.x)),
                                to_tf32(gelu_exact(acc[mt][nt][ai + 1] + d.y + p.y)));
            }
        }
    }
}

__device__ __forceinline__ void epi_bias_gelu(float* __restrict__ dst, int tid,
                                              const float acc[2][8][4],
                                              const float* __restrict__ bias) {
    const int w = tid >> 5, lane = tid & 31;
    const int wm = w & 3, wn = w >> 2;
    const int lr = lane >> 2, lc = lane & 3;
    float* cx = dst + (wm * 32 + lr) * XP + wn * 64 + 2 * lc;
#pragma unroll
    for (int nt = 0; nt < 8; nt++) {
        float2 bv = *(const float2*)(bias + wn * 64 + nt * 8 + 2 * lc);
#pragma unroll
        for (int mt = 0; mt < 2; mt++) {
            *(float2*)(cx + mt * (16 * XP) + nt * 8) =
                make_float2(to_tf32(gelu_exact(acc[mt][nt][0] + bv.x)),
                            to_tf32(gelu_exact(acc[mt][nt][1] + bv.y)));
            *(float2*)(cx + mt * (16 * XP) + 8 * XP + nt * 8) =
                make_float2(to_tf32(gelu_exact(acc[mt][nt][2] + bv.x)),
                            to_tf32(gelu_exact(acc[mt][nt][3] + bv.y)));
        }
    }
}

__device__ __forceinline__ void epi_mask_bias(float* __restrict__ dst, int tid,
                                              const float acc[2][8][4],
                                              const float* __restrict__ bias,
                                              const float* __restrict__ sMask) {
    const int w = tid >> 5, lane = tid & 31;
    const int wm = w & 3, wn = w >> 2;
    const int lr = lane >> 2, lc = lane & 3;
    float* cx = dst + (wm * 32 + lr) * XP + wn * 64 + 2 * lc;
#pragma unroll
    for (int mt = 0; mt < 2; mt++) {
        int r0 = wm * 32 + mt * 16 + lr;
        float mk0 = sMask[r0], mk8 = sMask[r0 + 8];
#pragma unroll
        for (int nt = 0; nt < 8; nt++) {
            float2 bv = *(const float2*)(bias + wn * 64 + nt * 8 + 2 * lc);
            *(float2*)(cx + mt * (16 * XP) + nt * 8) =
                make_float2(mk0 * (acc[mt][nt][0] + bv.x), mk0 * (acc[mt][nt][1] + bv.y));
            *(float2*)(cx + mt * (16 * XP) + 8 * XP + nt * 8) =
                make_float2(mk8 * (acc[mt][nt][2] + bv.x), mk8 * (acc[mt][nt][3] + bv.y));
        }
    }
}

// 64-row epilogue: global[row][col] = acc + optional bias (fp32), rows offset p0
__device__ __forceinline__ void epi_to_global64(float* __restrict__ gdst, int p0, int tid,
                                                const float acc[8][4],
                                                const float* __restrict__ bias) {
    const int w = tid >> 5, lane = tid & 31;
    const int wm = w & 3, wn = w >> 2;
    const int lr = lane >> 2, lc = lane & 3;
    const int r0 = wm * 16 + lr;
#pragma unroll
    for (int nt = 0; nt < 8; nt++) {
        int col = wn * 64 + nt * 8 + 2 * lc;
        float2 bv = bias ? *(const float2*)(bias + col) : make_float2(0.f, 0.f);
        *(float2*)(gdst + (size_t)(p0 + r0) * H + col) =
            make_float2(acc[nt][0] + bv.x, acc[nt][1] + bv.y);
        *(float2*)(gdst + (size_t)(p0 + r0 + 8) * H + col) =
            make_float2(acc[nt][2] + bv.x, acc[nt][3] + bv.y);
    }
}

__device__ __forceinline__ void epi_bias_gelu32(float* __restrict__ dst, int tid,
                                                const float acc[2][2][4],
                                                const float* __restrict__ bias) {
    const int w = tid >> 5, lane = tid & 31;
    const int lr = lane >> 2, lc = lane & 3;
    float* cx = dst + lr * XP + w * 16 + 2 * lc;
#pragma unroll
    for (int nt = 0; nt < 2; nt++) {
        float2 bv = *(const float2*)(bias + w * 16 + nt * 8 + 2 * lc);
#pragma unroll
        for (int mt = 0; mt < 2; mt++) {
            *(float2*)(cx + mt * (16 * XP) + nt * 8) =
                make_float2(to_tf32(gelu_exact(acc[mt][nt][0] + bv.x)),
                            to_tf32(gelu_exact(acc[mt][nt][1] + bv.y)));
            *(float2*)(cx + mt * (16 * XP) + 8 * XP + nt * 8) =
                make_float2(to_tf32(gelu_exact(acc[mt][nt][2] + bv.x)),
                            to_tf32(gelu_exact(acc[mt][nt][3] + bv.y)));
        }
    }
}

__device__ __forceinline__ void store_acc32(float* __restrict__ dst, int tid,
                                            const float acc[2][2][4]) {
    const int w = tid >> 5, lane = tid & 31;
    const int lr = lane >> 2, lc = lane & 3;
    float* cx = dst + lr * XP + w * 16 + 2 * lc;
#pragma unroll
    for (int mt = 0; mt < 2; mt++)
#pragma unroll
        for (int nt = 0; nt < 2; nt++) {
            *(float2*)(cx + mt * (16 * XP) + nt * 8) =
                make_float2(acc[mt][nt][0], acc[mt][nt][1]);
            *(float2*)(cx + mt * (16 * XP) + 8 * XP + nt * 8) =
                make_float2(acc[mt][nt][2], acc[mt][nt][3]);
        }
}

// ---------------- prep weights: transpose/fold + tf32 + k-pair permutation ----------------
__global__ void prep_weights(const float* __restrict__ W1, const float* __restrict__ W2,
                             const float* __restrict__ W3, const float* __restrict__ W11,
                             const float* __restrict__ W12, const float* __restrict__ W13,
                             const float* __restrict__ W_in, const float* __restrict__ W_out) {
    int idx = blockIdx.x * 256 + threadIdx.x;
    if (idx >= 19 * HH) return;
    int m = idx / HH;
    int r = (idx >> 7) & 127;
    int c = idx & 127;
    float v;
    switch (m) {
        case W_E1:  v = W1[(128 + c) * H + r] + W1[(384 + c) * H + r]; break;
        case W_2T:  v = W2[c * H + r]; break;
        case W_3T:  v = W3[c * H + r]; break;
        case W_11E: v = W11[(128 + c) * H + r]; break;
        case W_12T: v = W12[c * H + r]; break;
        case W_13T: v = W13[c * H + r]; break;
        case W_1V:  v = W1[c * H + r]; break;
        case W_1G:  v = W1[(256 + c) * H + r]; break;
        case W_1A:  v = W1[(512 + c) * H + r]; break;
        case W_11V: v = W11[c * H + r]; break;
        case W_11G: v = W11[(256 + c) * H + r]; break;
        default:
            if (m < W_OUTT) {
                int nc = m - W_INT;
                v = W_in[c * 512 + nc * 128 + r];
            } else {
                int kc = m - W_OUTT;
                v = W_out[(kc * 128 + c) * H + r];
            }
            break;
    }
    int kperm = (c & ~7) | ((c & 3) << 1) | ((c >> 2) & 1);
    g_Wt[m * HH + r * H + kperm] = to_tf32(v);
}

// ---------------- pre1: 64-row tiles, grid (64, 2) ----------------
// smem: sXa [0..8448) | sXb [8448..16896) | sW [16896..25600) -> 25600 floats (~102.4KB)
__global__ void __launch_bounds__(256)
pre1_mma(const float* __restrict__ hV, const float* __restrict__ hVa,
         const float* __restrict__ b1) {
    extern __shared__ float smf[];
    float* sXa = smf;
    float* sXb = smf + 8448;
    float* sW  = smf + 16896;
    const int tid = threadIdx.x;
    const int p0 = blockIdx.x * 64;
    const int z = blockIdx.y;
    const int r = tid >> 2, c0 = (tid & 3) * 32;

    {
        const float* a = hV + (size_t)(p0 + r) * H + c0;
        float* xa = sXa + r * XP + c0;
#pragma unroll
        for (int c = 0; c < 32; c += 4) {
            float4 v = *(const float4*)(a + c);
            xa[c] = to_tf32(v.x); xa[c+1] = to_tf32(v.y);
            xa[c+2] = to_tf32(v.z); xa[c+3] = to_tf32(v.w);
        }
        if (z == 1) {
            const float* b = hVa + (size_t)(p0 + r) * H + c0;
            float* xb = sXb + r * XP + c0;
#pragma unroll
            for (int c = 0; c < 32; c += 4) {
                float4 u = *(const float4*)(b + c);
                xb[c] = to_tf32(u.x); xb[c+1] = to_tf32(u.y);
                xb[c+2] = to_tf32(u.z); xb[c+3] = to_tf32(u.w);
            }
        }
    }

    float acc[8][4];
    zero_acc8(acc);
    if (z == 0) {
        gemm64(sXa, sW, g_Wt + W_1V * HH, tid, acc);
        epi_to_global64(g_D1, p0, tid, acc, b1);
    } else {
        gemm64(sXa, sW, g_Wt + W_1G * HH, tid, acc);
        gemm64(sXb, sW, g_Wt + W_1A * HH, tid, acc);
        epi_to_global64(g_P1, p0, tid, acc, (const float*)nullptr);
    }
}

// ---------------- pre2: 64-row tiles, grid (64, 2) ----------------
// smem: sXa [0..8448) | sW [8448..17152) -> 17152 floats (~68.6KB)
__global__ void __launch_bounds__(256)
pre2_mma(const float* __restrict__ hVf, const float* __restrict__ b11) {
    extern __shared__ float smf[];
    float* sXa = smf;
    float* sW  = smf + 8448;
    const int tid = threadIdx.x;
    const int p0 = blockIdx.x * 64;
    const int z = blockIdx.y;
    const int r = tid >> 2, c0 = (tid & 3) * 32;

    {
        const float* a = hVf + (size_t)(p0 + r) * H + c0;
        float* xa = sXa + r * XP + c0;
#pragma unroll
        for (int c = 0; c < 32; c += 4) {
            float4 v = *(const float4*)(a + c);
            xa[c] = to_tf32(v.x); xa[c+1] = to_tf32(v.y);
            xa[c+2] = to_tf32(v.z); xa[c+3] = to_tf32(v.w);
        }
    }

    float acc[8][4];
    zero_acc8(acc);
    if (z == 0) {
        gemm64(sXa, sW, g_Wt + W_11V * HH, tid, acc);
        epi_to_global64(g_D2, p0, tid, acc, b11);
    } else {
        gemm64(sXa, sW, g_Wt + W_11G * HH, tid, acc);
        epi_to_global64(g_P2, p0, tid, acc, (const float*)nullptr);
    }
}

// node/edge smem layout (floats):
#define SMEM_MLP 28176

// ---------------- node message MLP + sum_K + LN1 ----------------
__global__ void __launch_bounds__(256, 2)
node_mma_kernel(const float* __restrict__ hV, const float* __restrict__ hE,
                const float* __restrict__ b2, const float* __restrict__ b3,
                const float* __restrict__ g1, const float* __restrict__ be1,
                const float* __restrict__ maskA, const int* __restrict__ Eidx) {
    extern __shared__ float smf[];
    float* sX    = smf;
    float* sW    = smf + 16896;
    float* sAcc2 = sW;
    float* sD    = smf + 25600;
    float* sAcc  = smf + 26624;
    int*   sIdx  = (int*)(smf + 27648);
    float* sMask = smf + 28032;
    float* sRed  = smf + 28160;

    const int tid = threadIdx.x;
    const int p0 = blockIdx.x * 8;
    const int bb = p0 >> 11;
    const int r = tid >> 1, ch = (tid & 1) * 64;
    const float* P1b = g_P1 + (size_t)bb * NN * H;

    for (int i = tid; i < 8 * H; i += 256) {
        sD[i] = g_D1[(size_t)p0 * H + i];
        sAcc[i] = 0.f;
    }
    for (int i = tid; i < 8 * KNB; i += 256) sIdx[i] = Eidx[(size_t)p0 * KNB + i];

    float acc[2][8][4];

    for (int t = 0; t < 3; t++) {
        const int e0 = p0 * KNB + t * 128;
        float* xr = sX + r * XP + ch;

        __syncthreads();
        {
            const float* a = hE + (size_t)(e0 + r) * H + ch;
#pragma unroll
            for (int c = 0; c < 64; c += 4) {
                float4 v = *(const float4*)(a + c);
                xr[c] = to_tf32(v.x); xr[c+1] = to_tf32(v.y);
                xr[c+2] = to_tf32(v.z); xr[c+3] = to_tf32(v.w);
            }
        }
        if (tid < 128) sMask[tid] = maskA[e0 + tid];

        // GEMM1 + register epi1
        zero_acc(acc);
        gemm256(sX, sW, g_Wt + W_E1 * HH, tid, acc);
        __syncthreads();
        epi1_reg(sX, tid, t * 128, acc, P1b, sIdx + t * 128, sD);

        // GEMM2 + register epi2
        zero_acc(acc);
        gemm256(sX, sW, g_Wt + W_2T * HH, tid, acc);
        __syncthreads();
        epi_bias_gelu(sX, tid, acc, b2);

        // GEMM3 + register epi3 (mask)
        zero_acc(acc);
        gemm256(sX, sW, g_Wt + W_3T * HH, tid, acc);
        __syncthreads();
        epi_mask_bias(sX, tid, acc, b3, sMask);
        for (int i = tid; i < 2048; i += 256) sAcc2[i] = 0.f;
        __syncthreads();

        // segment-sum rows -> per-node partials
        {
            const int col = tid & 127, half = tid >> 7;
            int rr = half * 64;
            int nl = (t * 128 + rr) / KNB;
            int nxt = (nl + 1) * KNB - t * 128;
            float a = 0.f;
            for (; rr < half * 64 + 64; rr++) {
                if (rr == nxt) { sAcc2[half * 1024 + nl * 128 + col] = a; nl++; nxt += KNB; a = 0.f; }
                a += sX[rr * XP + col];
            }
            sAcc2[half * 1024 + nl * 128 + col] = a;
        }
        __syncthreads();
        for (int i = tid; i < 1024; i += 256)
            sAcc[i] += sAcc2[i] + sAcc2[1024 + i];
    }
    __syncthreads();

    // LN1: 2 nodes at a time
    for (int step = 0; step < 4; step++) {
        const int g = tid >> 7;
        const int n = step * 2 + g;
        const int c = tid & 127;
        float u = hV[(size_t)(p0 + n) * H + c] + sAcc[n * 128 + c] * (1.0f / 30.0f);
        float s = u;
#pragma unroll
        for (int off = 16; off > 0; off >>= 1) s += __shfl_xor_sync(0xffffffffu, s, off);
        if ((tid & 31) == 0) sRed[tid >> 5] = s;
        __syncthreads();
        float mean = (sRed[g*4] + sRed[g*4+1] + sRed[g*4+2] + sRed[g*4+3]) * (1.0f / H);
        float d = u - mean;
        float v2 = d * d;
#pragma unroll
        for (int off = 16; off > 0; off >>= 1) v2 += __shfl_xor_sync(0xffffffffu, v2, off);
        if ((tid & 31) == 0) sRed[8 + (tid >> 5)] = v2;
        __syncthreads();
        float var = (sRed[8+g*4] + sRed[8+g*4+1] + sRed[8+g*4+2] + sRed[8+g*4+3]) * (1.0f / H);
        g_hV1[(size_t)(p0 + n) * H + c] = d * rsqrtf(var + 1e-5f) * g1[c] + be1[c];
        __syncthreads();
    }
}

// ---------------- edge update MLP + LN3 ----------------
__global__ void __launch_bounds__(256, 2)
edge_mma_kernel(const float* __restrict__ hE,
                const float* __restrict__ b12, const float* __restrict__ b13,
                const float* __restrict__ g3, const float* __restrict__ be3,
                const int* __restrict__ Eidx, float* __restrict__ outE) {
    extern __shared__ float smf[];
    float* sX   = smf;
    float* sW   = smf + 16896;
    float* sD   = smf + 25600;
    int*   sIdx = (int*)(smf + 27648);

    const int tid = threadIdx.x;
    const int w = tid >> 5, lane = tid & 31;
    const int p0 = blockIdx.x * 8;
    const int bb = p0 >> 11;
    const int r = tid >> 1, ch = (tid & 1) * 64;
    const float* P2b = g_P2 + (size_t)bb * NN * H;

    for (int i = tid; i < 8 * H; i += 256) sD[i] = g_D2[(size_t)p0 * H + i];
    for (int i = tid; i < 8 * KNB; i += 256) sIdx[i] = Eidx[(size_t)p0 * KNB + i];

    float b13v[4], g3v[4], be3v[4];
#pragma unroll
    for (int q = 0; q < 4; q++) {
        b13v[q] = b13[lane + 32 * q];
        g3v[q]  = g3[lane + 32 * q];
        be3v[q] = be3[lane + 32 * q];
    }

    float acc[2][8][4];

    for (int t = 0; t < 3; t++) {
        const int e0 = p0 * KNB + t * 128;
        float* xr = sX + r * XP + ch;
        const float* arow = hE + (size_t)(e0 + r) * H + ch;

        __syncthreads();
#pragma unroll
        for (int c = 0; c < 64; c += 4) {
            float4 v = *(const float4*)(arow + c);
            xr[c] = to_tf32(v.x); xr[c+1] = to_tf32(v.y);
            xr[c+2] = to_tf32(v.z); xr[c+3] = to_tf32(v.w);
        }

        zero_acc(acc);
        gemm256(sX, sW, g_Wt + W_11E * HH, tid, acc);
        __syncthreads();
        epi1_reg(sX, tid, t * 128, acc, P2b, sIdx + t * 128, sD);

        zero_acc(acc);
        gemm256(sX, sW, g_Wt + W_12T * HH, tid, acc);
        __syncthreads();
        epi_bias_gelu(sX, tid, acc, b12);

        zero_acc(acc);
        gemm256(sX, sW, g_Wt + W_13T * HH, tid, acc);
        __syncthreads();
        store_acc(sX, tid, acc);
        __syncthreads();

        // LN3 with fused b13 + hE residual: each warp 16 rows
        for (int rr = w * 16; rr < w * 16 + 16; rr++) {
            const float* he = hE + (size_t)(e0 + rr) * H;
            float v[4];
            float ssum = 0.f;
#pragma unroll
            for (int q = 0; q < 4; q++) {
                v[q] = sX[rr * XP + lane + 32 * q] + b13v[q] + he[lane + 32 * q];
                ssum += v[q];
            }
#pragma unroll
            for (int off = 16; off > 0; off >>= 1) ssum += __shfl_xor_sync(0xffffffffu, ssum, off);
            float mean = ssum * (1.0f / H);
            float vs = 0.f;
#pragma unroll
            for (int q = 0; q < 4; q++) { v[q] -= mean; vs += v[q] * v[q]; }
#pragma unroll
            for (int off = 16; off > 0; off >>= 1) vs += __shfl_xor_sync(0xffffffffu, vs, off);
            float rs = rsqrtf(vs * (1.0f / H) + 1e-5f);
#pragma unroll
            for (int q = 0; q < 4; q++)
                outE[(size_t)(e0 + rr) * H + lane + 32 * q] = v[q] * rs * g3v[q] + be3v[q];
        }
        __syncthreads();
    }
}

// ---------------- FFN (tensor): 32 nodes/CTA, grid 128 ----------------
__global__ void __launch_bounds__(256)
ffn_mma(const float* __restrict__ b_in, const float* __restrict__ b_out,
        const float* __restrict__ g2, const float* __restrict__ be2,
        const float* __restrict__ maskV, float* __restrict__ outV) {
    extern __shared__ float smf[];
    float* sXa = smf;
    float* sXb = smf + 4224;
    float* sW  = smf + 8448;
    const int tid = threadIdx.x;
    const int w = tid >> 5, lane = tid & 31;
    const int p0 = blockIdx.x * 32;

    {
        const int r = tid >> 3, c0 = (tid & 7) * 16;
        const float* a = g_hV1 + (size_t)(p0 + r) * H + c0;
        float* xa = sXa + r * XP + c0;
#pragma unroll
        for (int c = 0; c < 16; c += 4) {
            float4 v = *(const float4*)(a + c);
            xa[c] = to_tf32(v.x); xa[c+1] = to_tf32(v.y);
            xa[c+2] = to_tf32(v.z); xa[c+3] = to_tf32(v.w);
        }
    }

    float acc[2][2][4], acc2[2][2][4];
    zero_acc32(acc2);
#pragma unroll
    for (int nc = 0; nc < 4; nc++) {
        zero_acc32(acc);
        gemm32(sXa, sW, g_Wt + (W_INT + nc) * HH, tid, acc);
        __syncthreads();
        epi_bias_gelu32(sXb, tid, acc, b_in + nc * 128);
        gemm32(sXb, sW, g_Wt + (W_OUTT + nc) * HH, tid, acc2);
    }
    __syncthreads();
    store_acc32(sXb, tid, acc2);
    __syncthreads();

    for (int rr = w * 4; rr < w * 4 + 4; rr++) {
        const size_t row = p0 + rr;
        const float* res = g_hV1 + row * H;
        float u[4];
        float s = 0.f;
#pragma unroll
        for (int q = 0; q < 4; q++) {
            int c = lane + 32 * q;
            u[q] = sXb[rr * XP + c] + res[c] + b_out[c];
            s += u[q];
        }
#pragma unroll
        for (int off = 16; off > 0; off >>= 1) s += __shfl_xor_sync(0xffffffffu, s, off);
        float mean = s * (1.0f / H);
        float vs = 0.f;
#pragma unroll
        for (int q = 0; q < 4; q++) { u[q] -= mean; vs += u[q] * u[q]; }
#pragma unroll
        for (int off = 16; off > 0; off >>= 1) vs += __shfl_xor_sync(0xffffffffu, vs, off);
        float rs = rsqrtf(vs * (1.0f / H) + 1e-5f);
        float mv = maskV[row];
#pragma unroll
        for (int q = 0; q < 4; q++) {
            int c = lane + 32 * q;
            outV[row * H + c] = (u[q] * rs * g2[c] + be2[c]) * mv;
        }
    }
}

// ---------------- launch ----------------
extern "C" void kernel_launch(void* const* d_in, const int* in_sizes, int n_in,
                              void* d_out, int out_size) {
    const float* hV    = (const float*)d_in[0];
    const float* hVa   = (const float*)d_in[1];
    const float* hE    = (const float*)d_in[2];
    const float* W1    = (const float*)d_in[3];
    const float* b1    = (const float*)d_in[4];
    const float* W2    = (const float*)d_in[5];
    const float* b2    = (const float*)d_in[6];
    const float* W3    = (const float*)d_in[7];
    const float* b3    = (const float*)d_in[8];
    const float* W11   = (const float*)d_in[9];
    const float* b11   = (const float*)d_in[10];
    const float* W12   = (const float*)d_in[11];
    const float* b12   = (const float*)d_in[12];
    const float* W13   = (const float*)d_in[13];
    const float* b13   = (const float*)d_in[14];
    const float* W_in  = (const float*)d_in[15];
    const float* b_in  = (const float*)d_in[16];
    const float* W_out = (const float*)d_in[17];
    const float* b_out = (const float*)d_in[18];
    const float* g1    = (const float*)d_in[19];
    const float* be1   = (const float*)d_in[20];
    const float* g2    = (const float*)d_in[21];
    const float* be2   = (const float*)d_in[22];
    const float* g3    = (const float*)d_in[23];
    const float* be3   = (const float*)d_in[24];
    const float* maskV = (const float*)d_in[25];
    const float* maskA = (const float*)d_in[26];
    const int*   Eidx  = (const int*)d_in[27];

    const int BN = in_sizes[0] / H;   // 4096
    float* outV = (float*)d_out;
    float* outE = (float*)d_out + (size_t)BN * H;

    const size_t smemMLP  = SMEM_MLP * sizeof(float);  // ~110.1 KB (2 CTAs/SM)
    const size_t smemPRE1 = 25600 * sizeof(float);     // 102.4 KB
    const size_t smemPRE2 = 17152 * sizeof(float);     // 68.6 KB
    const size_t smemFFN  = 17152 * sizeof(float);     // 68.6 KB

    cudaFuncSetAttribute(node_mma_kernel, cudaFuncAttributeMaxDynamicSharedMemorySize, (int)smemMLP);
    cudaFuncSetAttribute(edge_mma_kernel, cudaFuncAttributeMaxDynamicSharedMemorySize, (int)smemMLP);
    cudaFuncSetAttribute(pre1_mma, cudaFuncAttributeMaxDynamicSharedMemorySize, (int)smemPRE1);
    cudaFuncSetAttribute(pre2_mma, cudaFuncAttributeMaxDynamicSharedMemorySize, (int)smemPRE2);
    cudaFuncSetAttribute(ffn_mma,  cudaFuncAttributeMaxDynamicSharedMemorySize, (int)smemFFN);

    prep_weights<<<(19 * HH + 255) / 256, 256>>>(W1, W2, W3, W11, W12, W13, W_in, W_out);
    pre1_mma<<<dim3(BN / 64, 2), 256, smemPRE1>>>(hV, hVa, b1);
    node_mma_kernel<<<BN / 8, 256, smemMLP>>>(hV, hE, b2, b3, g1, be1, maskA, Eidx);
    ffn_mma<<<BN / 32, 256, smemFFN>>>(b_in, b_out, g2, be2, maskV, outV);
    pre2_mma<<<dim3(BN / 64, 2), 256, smemPRE2>>>(outV, b11);
    edge_mma_kernel<<<BN / 8, 256, smemMLP>>>(hE, b12, b13, g3, be3, Eidx, outE);
}

// round 15
// speedup vs baseline: 1.2945x; 1.0493x over previous
#include <cuda_runtime.h>
#include <cstdint>
#include <math.h>

#define H      128
#define HH     (H * H)
#define KNB    48
#define NN     2048
#define BNTOT  4096
#define XP     132          // activation tile pitch (floats)
#define WP     68           // weight tile pitch (floats, sync path)
#define WPQ    36           // weight quarter pitch (floats, cp.async path)

// weight matrix slots in g_Wt (all 128x128 [n][kperm], tf32-rounded)
#define W_E1   0
#define W_2T   1
#define W_3T   2
#define W_11E  3
#define W_12T  4
#define W_13T  5
#define W_1V   6
#define W_1G   7
#define W_1A   8
#define W_11V  9
#define W_11G  10
#define W_INT  11   // 11..14: W_in^T chunks
#define W_OUTT 15   // 15..18: W_out^T chunks

__device__ float g_Wt[19 * HH];
__device__ float g_D1[BNTOT * H];
__device__ float g_P1[BNTOT * H];
__device__ float g_D2[BNTOT * H];
__device__ float g_P2[BNTOT * H];
__device__ float g_hV1[BNTOT * H];

__device__ __forceinline__ float to_tf32(float x) {
    uint32_t u;
    asm("cvt.rna.tf32.f32 %0, %1;" : "=r"(u) : "f"(x));
    return __uint_as_float(u);
}

__device__ __forceinline__ float gelu_exact(float x) {
    return 0.5f * x * (1.0f + erff(x * 0.70710678118654752f));
}

__device__ __forceinline__ void mma_tf32(float d[4], const uint32_t a[4], const uint32_t b[2]) {
    asm volatile("mma.sync.aligned.m16n8k8.row.col.f32.tf32.tf32.f32 "
                 "{%0,%1,%2,%3}, {%4,%5,%6,%7}, {%8,%9}, {%0,%1,%2,%3};"
                 : "+f"(d[0]), "+f"(d[1]), "+f"(d[2]), "+f"(d[3])
                 : "r"(a[0]), "r"(a[1]), "r"(a[2]), "r"(a[3]), "r"(b[0]), "r"(b[1]));
}

// ---------------- async stage of one 32-k quarter (128n x 32k) into buf ----------------
__device__ __forceinline__ void stage_q_async(float* __restrict__ buf,
                                              const float* __restrict__ Wg, int q, int tid) {
    uint32_t base = (uint32_t)__cvta_generic_to_shared(buf);
#pragma unroll
    for (int i = 0; i < 4; i++) {
        int idx = tid + 256 * i;          // 0..1023
        int n = idx >> 3, qd = idx & 7;   // 8 float4 per 32-float row
        asm volatile("cp.async.cg.shared.global [%0], [%1], 16;"
                     :: "r"(base + (uint32_t)((n * WPQ + qd * 4) * 4)),
                        "l"(Wg + n * H + q * 32 + qd * 4));
    }
    asm volatile("cp.async.commit_group;");
}

// ---------------- 128x128x128 tf32 GEMM, double-buffered async staging ----------------
// 256 threads (8 warps, 4m x 2n). B is k-pair-permuted -> single float2 LDS.
__device__ __forceinline__ void gemm256_db(const float* __restrict__ sX,
                                           float* __restrict__ sW0, float* __restrict__ sW1,
                                           const float* __restrict__ Wg, int tid,
                                           float acc[2][8][4]) {
    const int w = tid >> 5, lane = tid & 31;
    const int wm = w & 3, wn = w >> 2;
    const int lr = lane >> 2, lc = lane & 3;
    const float* sXw = sX + (wm * 32 + lr) * XP + lc;

    stage_q_async(sW0, Wg, 0, tid);
#pragma unroll
    for (int q = 0; q < 4; q++) {
        asm volatile("cp.async.wait_group 0;");
        __syncthreads();
        if (q < 3) stage_q_async((q & 1) ? sW0 : sW1, Wg, q + 1, tid);
        const float* bq = (q & 1) ? sW1 : sW0;
        const float* sWb = bq + (wn * 64 + lr) * WPQ + 2 * lc;
#pragma unroll
        for (int k8 = 0; k8 < 4; k8++) {
            const int kl = k8 * 8;
            uint32_t a[2][4];
#pragma unroll
            for (int mt = 0; mt < 2; mt++) {
                const float* ap = sXw + mt * (16 * XP) + q * 32 + kl;
                a[mt][0] = __float_as_uint(ap[0]);
                a[mt][1] = __float_as_uint(ap[8 * XP]);
                a[mt][2] = __float_as_uint(ap[4]);
                a[mt][3] = __float_as_uint(ap[8 * XP + 4]);
            }
#pragma unroll
            for (int nt = 0; nt < 8; nt++) {
                float2 bv = *(const float2*)(sWb + nt * (8 * WPQ) + kl);
                uint32_t b[2] = {__float_as_uint(bv.x), __float_as_uint(bv.y)};
                mma_tf32(acc[0][nt], a[0], b);
                mma_tf32(acc[1][nt], a[1], b);
            }
        }
    }
}

// ---------------- synchronous stage (pre/ffn path) ----------------
__device__ __forceinline__ void stage_W_half(float* __restrict__ sW,
                                             const float* __restrict__ Wg, int h, int tid) {
#pragma unroll
    for (int i = 0; i < 8; i++) {
        int idx = tid + 256 * i;
        int n = idx >> 4, q = idx & 15;
        float4 v = *(const float4*)(Wg + n * H + h * 64 + q * 4);
        *(float4*)(sW + n * WP + q * 4) = v;
    }
}

// ---------------- 64x128x128 tf32 GEMM, 256 threads (4m x 2n, warp tile 16x64) ----------
__device__ __forceinline__ void gemm64(const float* __restrict__ sX, float* __restrict__ sW,
                                       const float* __restrict__ Wg, int tid,
                                       float acc[8][4]) {
    const int w = tid >> 5, lane = tid & 31;
    const int wm = w & 3, wn = w >> 2;
    const int lr = lane >> 2, lc = lane & 3;
    const float* sXw = sX + (wm * 16 + lr) * XP + lc;
    const float* sWb = sW + (wn * 64 + lr) * WP + 2 * lc;
#pragma unroll
    for (int h = 0; h < 2; h++) {
        __syncthreads();
        stage_W_half(sW, Wg, h, tid);
        __syncthreads();
#pragma unroll
        for (int k8 = 0; k8 < 8; k8++) {
            const int kl = k8 * 8;
            const float* ap = sXw + h * 64 + kl;
            uint32_t a[4];
            a[0] = __float_as_uint(ap[0]);
            a[1] = __float_as_uint(ap[8 * XP]);
            a[2] = __float_as_uint(ap[4]);
            a[3] = __float_as_uint(ap[8 * XP + 4]);
#pragma unroll
            for (int nt = 0; nt < 8; nt++) {
                float2 bv = *(const float2*)(sWb + nt * (8 * WP) + kl);
                uint32_t b[2] = {__float_as_uint(bv.x), __float_as_uint(bv.y)};
                mma_tf32(acc[nt], a, b);
            }
        }
    }
}

// ---------------- 32x128x128 tf32 GEMM, 256 threads (8 warps across n) ----------------
__device__ __forceinline__ void gemm32(const float* __restrict__ sX, float* __restrict__ sW,
                                       const float* __restrict__ Wg, int tid,
                                       float acc[2][2][4]) {
    const int w = tid >> 5, lane = tid & 31;
    const int lr = lane >> 2, lc = lane & 3;
    const float* sXw = sX + lr * XP + lc;
    const float* sWb = sW + (w * 16 + lr) * WP + 2 * lc;
#pragma unroll
    for (int h = 0; h < 2; h++) {
        __syncthreads();
        stage_W_half(sW, Wg, h, tid);
        __syncthreads();
#pragma unroll
        for (int k8 = 0; k8 < 8; k8++) {
            const int kl = k8 * 8;
            uint32_t a[2][4];
#pragma unroll
            for (int mt = 0; mt < 2; mt++) {
                const float* ap = sXw + mt * (16 * XP) + h * 64 + kl;
                a[mt][0] = __float_as_uint(ap[0]);
                a[mt][1] = __float_as_uint(ap[8 * XP]);
                a[mt][2] = __float_as_uint(ap[4]);
                a[mt][3] = __float_as_uint(ap[8 * XP + 4]);
            }
#pragma unroll
            for (int nt = 0; nt < 2; nt++) {
                float2 bv = *(const float2*)(sWb + nt * (8 * WP) + kl);
                uint32_t b[2] = {__float_as_uint(bv.x), __float_as_uint(bv.y)};
                mma_tf32(acc[0][nt], a[0], b);
                mma_tf32(acc[1][nt], a[1], b);
            }
        }
    }
}

__device__ __forceinline__ void zero_acc(float acc[2][8][4]) {
#pragma unroll
    for (int mt = 0; mt < 2; mt++)
#pragma unroll
        for (int nt = 0; nt < 8; nt++)
#pragma unroll
            for (int q = 0; q < 4; q++) acc[mt][nt][q] = 0.f;
}

__device__ __forceinline__ void zero_acc8(float acc[8][4]) {
#pragma unroll
    for (int nt = 0; nt < 8; nt++)
#pragma unroll
        for (int q = 0; q < 4; q++) acc[nt][q] = 0.f;
}

__device__ __forceinline__ void zero_acc32(float acc[2][2][4]) {
#pragma unroll
    for (int mt = 0; mt < 2; mt++)
#pragma unroll
        for (int nt = 0; nt < 2; nt++)
#pragma unroll
            for (int q = 0; q < 4; q++) acc[mt][nt][q] = 0.f;
}

__device__ __forceinline__ void store_acc(float* __restrict__ dst, int tid,
                                          const float acc[2][8][4]) {
    const int w = tid >> 5, lane = tid & 31;
    const int wm = w & 3, wn = w >> 2;
    const int lr = lane >> 2, lc = lane & 3;
    float* cx = dst + (wm * 32 + lr) * XP + wn * 64 + 2 * lc;
#pragma unroll
    for (int mt = 0; mt < 2; mt++)
#pragma unroll
        for (int nt = 0; nt < 8; nt++) {
            *(float2*)(cx + mt * (16 * XP) + nt * 8) =
                make_float2(acc[mt][nt][0], acc[mt][nt][1]);
            *(float2*)(cx + mt * (16 * XP) + 8 * XP + nt * 8) =
                make_float2(acc[mt][nt][2], acc[mt][nt][3]);
        }
}

// register epi1: sX = to_tf32(gelu(acc + sD[node(row)] + P[src(row)]))
__device__ __forceinline__ void epi1_reg(float* __restrict__ sX, int tid, int t128,
                                         const float acc[2][8][4],
                                         const float* __restrict__ Pbase,
                                         const int* __restrict__ sIdxT,
                                         const float* __restrict__ sD) {
    const int w = tid >> 5, lane = tid & 31;
    const int wm = w & 3, wn = w >> 2;
    const int lr = lane >> 2, lc = lane & 3;
#pragma unroll
    for (int mt = 0; mt < 2; mt++) {
#pragma unroll
        for (int hf = 0; hf < 2; hf++) {
            int r = wm * 32 + mt * 16 + lr + hf * 8;
            int src = sIdxT[r];
            int nl = (t128 + r) / KNB;
            const float* pr = Pbase + (size_t)src * H;
            const float* dn = sD + nl * H;
            float* xrow = sX + r * XP;
            const int ai = hf * 2;
#pragma unroll
            for (int nt = 0; nt < 8; nt++) {
                int col = wn * 64 + nt * 8 + 2 * lc;
                float2 p = *(const float2*)(pr + col);
                float2 d = *(const float2*)(dn + col);
                *(float2*)(xrow + col) =
                    make_float2(to_tf32(gelu_exact(acc[mt][nt][ai] + d.x + p.x)),
                                to_tf32(gelu_exact(acc[mt][nt][ai + 1] + d.y + p.y)));
            }
        }
    }
}

__device__ __forceinline__ void epi_bias_gelu(float* __restrict__ dst, int tid,
                                              const float acc[2][8][4],
                                              const float* __restrict__ bias) {
    const int w = tid >> 5, lane = tid & 31;
    const int wm = w & 3, wn = w >> 2;
    const int lr = lane >> 2, lc = lane & 3;
    float* cx = dst + (wm * 32 + lr) * XP + wn * 64 + 2 * lc;
#pragma unroll
    for (int nt = 0; nt < 8; nt++) {
        float2 bv = *(const float2*)(bias + wn * 64 + nt * 8 + 2 * lc);
#pragma unroll
        for (int mt = 0; mt < 2; mt++) {
            *(float2*)(cx + mt * (16 * XP) + nt * 8) =
                make_float2(to_tf32(gelu_exact(acc[mt][nt][0] + bv.x)),
                            to_tf32(gelu_exact(acc[mt][nt][1] + bv.y)));
            *(float2*)(cx + mt * (16 * XP) + 8 * XP + nt * 8) =
                make_float2(to_tf32(gelu_exact(acc[mt][nt][2] + bv.x)),
                            to_tf32(gelu_exact(acc[mt][nt][3] + bv.y)));
        }
    }
}

__device__ __forceinline__ void epi_mask_bias(float* __restrict__ dst, int tid,
                                              const float acc[2][8][4],
                                              const float* __restrict__ bias,
                                              const float* __restrict__ sMask) {
    const int w = tid >> 5, lane = tid & 31;
    const int wm = w & 3, wn = w >> 2;
    const int lr = lane >> 2, lc = lane & 3;
    float* cx = dst + (wm * 32 + lr) * XP + wn * 64 + 2 * lc;
#pragma unroll
    for (int mt = 0; mt < 2; mt++) {
        int r0 = wm * 32 + mt * 16 + lr;
        float mk0 = sMask[r0], mk8 = sMask[r0 + 8];
#pragma unroll
        for (int nt = 0; nt < 8; nt++) {
            float2 bv = *(const float2*)(bias + wn * 64 + nt * 8 + 2 * lc);
            *(float2*)(cx + mt * (16 * XP) + nt * 8) =
                make_float2(mk0 * (acc[mt][nt][0] + bv.x), mk0 * (acc[mt][nt][1] + bv.y));
            *(float2*)(cx + mt * (16 * XP) + 8 * XP + nt * 8) =
                make_float2(mk8 * (acc[mt][nt][2] + bv.x), mk8 * (acc[mt][nt][3] + bv.y));
        }
    }
}

// 64-row epilogue: global[row][col] = acc + optional bias (fp32), rows offset p0
__device__ __forceinline__ void epi_to_global64(float* __restrict__ gdst, int p0, int tid,
                                                const float acc[8][4],
                                                const float* __restrict__ bias) {
    const int w = tid >> 5, lane = tid & 31;
    const int wm = w & 3, wn = w >> 2;
    const int lr = lane >> 2, lc = lane & 3;
    const int r0 = wm * 16 + lr;
#pragma unroll
    for (int nt = 0; nt < 8; nt++) {
        int col = wn * 64 + nt * 8 + 2 * lc;
        float2 bv = bias ? *(const float2*)(bias + col) : make_float2(0.f, 0.f);
        *(float2*)(gdst + (size_t)(p0 + r0) * H + col) =
            make_float2(acc[nt][0] + bv.x, acc[nt][1] + bv.y);
        *(float2*)(gdst + (size_t)(p0 + r0 + 8) * H + col) =
            make_float2(acc[nt][2] + bv.x, acc[nt][3] + bv.y);
    }
}

__device__ __forceinline__ void epi_bias_gelu32(float* __restrict__ dst, int tid,
                                                const float acc[2][2][4],
                                                const float* __restrict__ bias) {
    const int w = tid >> 5, lane = tid & 31;
    const int lr = lane >> 2, lc = lane & 3;
    float* cx = dst + lr * XP + w * 16 + 2 * lc;
#pragma unroll
    for (int nt = 0; nt < 2; nt++) {
        float2 bv = *(const float2*)(bias + w * 16 + nt * 8 + 2 * lc);
#pragma unroll
        for (int mt = 0; mt < 2; mt++) {
            *(float2*)(cx + mt * (16 * XP) + nt * 8) =
                make_float2(to_tf32(gelu_exact(acc[mt][nt][0] + bv.x)),
                            to_tf32(gelu_exact(acc[mt][nt][1] + bv.y)));
            *(float2*)(cx + mt * (16 * XP) + 8 * XP + nt * 8) =
                make_float2(to_tf32(gelu_exact(acc[mt][nt][2] + bv.x)),
                            to_tf32(gelu_exact(acc[mt][nt][3] + bv.y)));
        }
    }
}

__device__ __forceinline__ void store_acc32(float* __restrict__ dst, int tid,
                                            const float acc[2][2][4]) {
    const int w = tid >> 5, lane = tid & 31;
    const int lr = lane >> 2, lc = lane & 3;
    float* cx = dst + lr * XP + w * 16 + 2 * lc;
#pragma unroll
    for (int mt = 0; mt < 2; mt++)
#pragma unroll
        for (int nt = 0; nt < 2; nt++) {
            *(float2*)(cx + mt * (16 * XP) + nt * 8) =
                make_float2(acc[mt][nt][0], acc[mt][nt][1]);
            *(float2*)(cx + mt * (16 * XP) + 8 * XP + nt * 8) =
                make_float2(acc[mt][nt][2], acc[mt][nt][3]);
        }
}

// ---------------- prep weights: transpose/fold + tf32 + k-pair permutation ----------------
__global__ void prep_weights(const float* __restrict__ W1, const float* __restrict__ W2,
                             const float* __restrict__ W3, const float* __restrict__ W11,
                             const float* __restrict__ W12, const float* __restrict__ W13,
                             const float* __restrict__ W_in, const float* __restrict__ W_out) {
    int idx = blockIdx.x * 256 + threadIdx.x;
    if (idx >= 19 * HH) return;
    int m = idx / HH;
    int r = (idx >> 7) & 127;
    int c = idx & 127;
    float v;
    switch (m) {
        case W_E1:  v = W1[(128 + c) * H + r] + W1[(384 + c) * H + r]; break;
        case W_2T:  v = W2[c * H + r]; break;
        case W_3T:  v = W3[c * H + r]; break;
        case W_11E: v = W11[(128 + c) * H + r]; break;
        case W_12T: v = W12[c * H + r]; break;
        case W_13T: v = W13[c * H + r]; break;
        case W_1V:  v = W1[c * H + r]; break;
        case W_1G:  v = W1[(256 + c) * H + r]; break;
        case W_1A:  v = W1[(512 + c) * H + r]; break;
        case W_11V: v = W11[c * H + r]; break;
        case W_11G: v = W11[(256 + c) * H + r]; break;
        default:
            if (m < W_OUTT) {
                int nc = m - W_INT;
                v = W_in[c * 512 + nc * 128 + r];
            } else {
                int kc = m - W_OUTT;
                v = W_out[(kc * 128 + c) * H + r];
            }
            break;
    }
    int kperm = (c & ~7) | ((c & 3) << 1) | ((c >> 2) & 1);
    g_Wt[m * HH + r * H + kperm] = to_tf32(v);
}

// ---------------- pre1: 64-row tiles, grid (64, 2) ----------------
// smem: sXa [0..8448) | sXb [8448..16896) | sW [16896..25600)
__global__ void __launch_bounds__(256)
pre1_mma(const float* __restrict__ hV, const float* __restrict__ hVa,
         const float* __restrict__ b1) {
    extern __shared__ float smf[];
    float* sXa = smf;
    float* sXb = smf + 8448;
    float* sW  = smf + 16896;
    const int tid = threadIdx.x;
    const int p0 = blockIdx.x * 64;
    const int z = blockIdx.y;
    const int r = tid >> 2, c0 = (tid & 3) * 32;

    {
        const float* a = hV + (size_t)(p0 + r) * H + c0;
        float* xa = sXa + r * XP + c0;
#pragma unroll
        for (int c = 0; c < 32; c += 4) {
            float4 v = *(const float4*)(a + c);
            xa[c] = to_tf32(v.x); xa[c+1] = to_tf32(v.y);
            xa[c+2] = to_tf32(v.z); xa[c+3] = to_tf32(v.w);
        }
        if (z == 1) {
            const float* b = hVa + (size_t)(p0 + r) * H + c0;
            float* xb = sXb + r * XP + c0;
#pragma unroll
            for (int c = 0; c < 32; c += 4) {
                float4 u = *(const float4*)(b + c);
                xb[c] = to_tf32(u.x); xb[c+1] = to_tf32(u.y);
                xb[c+2] = to_tf32(u.z); xb[c+3] = to_tf32(u.w);
            }
        }
    }

    float acc[8][4];
    zero_acc8(acc);
    if (z == 0) {
        gemm64(sXa, sW, g_Wt + W_1V * HH, tid, acc);
        epi_to_global64(g_D1, p0, tid, acc, b1);
    } else {
        gemm64(sXa, sW, g_Wt + W_1G * HH, tid, acc);
        gemm64(sXb, sW, g_Wt + W_1A * HH, tid, acc);
        epi_to_global64(g_P1, p0, tid, acc, (const float*)nullptr);
    }
}

// ---------------- pre2: 64-row tiles, grid (64, 2) ----------------
__global__ void __launch_bounds__(256)
pre2_mma(const float* __restrict__ hVf, const float* __restrict__ b11) {
    extern __shared__ float smf[];
    float* sXa = smf;
    float* sW  = smf + 8448;
    const int tid = threadIdx.x;
    const int p0 = blockIdx.x * 64;
    const int z = blockIdx.y;
    const int r = tid >> 2, c0 = (tid & 3) * 32;

    {
        const float* a = hVf + (size_t)(p0 + r) * H + c0;
        float* xa = sXa + r * XP + c0;
#pragma unroll
        for (int c = 0; c < 32; c += 4) {
            float4 v = *(const float4*)(a + c);
            xa[c] = to_tf32(v.x); xa[c+1] = to_tf32(v.y);
            xa[c+2] = to_tf32(v.z); xa[c+3] = to_tf32(v.w);
        }
    }

    float acc[8][4];
    zero_acc8(acc);
    if (z == 0) {
        gemm64(sXa, sW, g_Wt + W_11V * HH, tid, acc);
        epi_to_global64(g_D2, p0, tid, acc, b11);
    } else {
        gemm64(sXa, sW, g_Wt + W_11G * HH, tid, acc);
        epi_to_global64(g_P2, p0, tid, acc, (const float*)nullptr);
    }
}

// node smem (floats): sX 0..16896 | sW0 16896..21504 | sW1 21504..26112 |
//   sD 26112..27136 | sAcc 27136..28160 | sIdx 28160..28544 (int) |
//   sMask 28544..28672 ; sAcc2 aliases sW0 (2048) ; sRed aliases smf+18944
#define SMEM_NODE 28672
// edge smem: sX | sW0 | sW1 | sD 26112..27136 | sIdx 27136..27520
#define SMEM_EDGE 27520

// ---------------- node message MLP + sum_K + LN1 ----------------
__global__ void __launch_bounds__(256, 2)
node_mma_kernel(const float* __restrict__ hV, const float* __restrict__ hE,
                const float* __restrict__ b2, const float* __restrict__ b3,
                const float* __restrict__ g1, const float* __restrict__ be1,
                const float* __restrict__ maskA, const int* __restrict__ Eidx) {
    extern __shared__ float smf[];
    float* sX    = smf;
    float* sW0   = smf + 16896;
    float* sW1   = smf + 21504;
    float* sAcc2 = sW0;                  // used after GEMM3 (buffers dead)
    float* sRed  = smf + 18944;          // used only in LN phase
    float* sD    = smf + 26112;
    float* sAcc  = smf + 27136;
    int*   sIdx  = (int*)(smf + 28160);
    float* sMask = smf + 28544;

    const int tid = threadIdx.x;
    const int p0 = blockIdx.x * 8;
    const int bb = p0 >> 11;
    const int r = tid >> 1, ch = (tid & 1) * 64;
    const float* P1b = g_P1 + (size_t)bb * NN * H;

    for (int i = tid; i < 8 * H; i += 256) {
        sD[i] = g_D1[(size_t)p0 * H + i];
        sAcc[i] = 0.f;
    }
    for (int i = tid; i < 8 * KNB; i += 256) sIdx[i] = Eidx[(size_t)p0 * KNB + i];

    float acc[2][8][4];

    for (int t = 0; t < 3; t++) {
        const int e0 = p0 * KNB + t * 128;
        float* xr = sX + r * XP + ch;

        __syncthreads();
        {
            const float* a = hE + (size_t)(e0 + r) * H + ch;
#pragma unroll
            for (int c = 0; c < 64; c += 4) {
                float4 v = *(const float4*)(a + c);
                xr[c] = to_tf32(v.x); xr[c+1] = to_tf32(v.y);
                xr[c+2] = to_tf32(v.z); xr[c+3] = to_tf32(v.w);
            }
        }
        if (tid < 128) sMask[tid] = maskA[e0 + tid];

        // GEMM1 + register epi1
        zero_acc(acc);
        gemm256_db(sX, sW0, sW1, g_Wt + W_E1 * HH, tid, acc);
        __syncthreads();
        epi1_reg(sX, tid, t * 128, acc, P1b, sIdx + t * 128, sD);

        // GEMM2 + register epi2
        zero_acc(acc);
        gemm256_db(sX, sW0, sW1, g_Wt + W_2T * HH, tid, acc);
        __syncthreads();
        epi_bias_gelu(sX, tid, acc, b2);

        // GEMM3 + register epi3 (mask)
        zero_acc(acc);
        gemm256_db(sX, sW0, sW1, g_Wt + W_3T * HH, tid, acc);
        __syncthreads();
        epi_mask_bias(sX, tid, acc, b3, sMask);
        for (int i = tid; i < 2048; i += 256) sAcc2[i] = 0.f;
        __syncthreads();

        // segment-sum rows -> per-node partials
        {
            const int col = tid & 127, half = tid >> 7;
            int rr = half * 64;
            int nl = (t * 128 + rr) / KNB;
            int nxt = (nl + 1) * KNB - t * 128;
            float a = 0.f;
            for (; rr < half * 64 + 64; rr++) {
                if (rr == nxt) { sAcc2[half * 1024 + nl * 128 + col] = a; nl++; nxt += KNB; a = 0.f; }
                a += sX[rr * XP + col];
            }
            sAcc2[half * 1024 + nl * 128 + col] = a;
        }
        __syncthreads();
        for (int i = tid; i < 1024; i += 256)
            sAcc[i] += sAcc2[i] + sAcc2[1024 + i];
    }
    __syncthreads();

    // LN1: 2 nodes at a time
    for (int step = 0; step < 4; step++) {
        const int g = tid >> 7;
        const int n = step * 2 + g;
        const int c = tid & 127;
        float u = hV[(size_t)(p0 + n) * H + c] + sAcc[n * 128 + c] * (1.0f / 30.0f);
        float s = u;
#pragma unroll
        for (int off = 16; off > 0; off >>= 1) s += __shfl_xor_sync(0xffffffffu, s, off);
        if ((tid & 31) == 0) sRed[tid >> 5] = s;
        __syncthreads();
        float mean = (sRed[g*4] + sRed[g*4+1] + sRed[g*4+2] + sRed[g*4+3]) * (1.0f / H);
        float d = u - mean;
        float v2 = d * d;
#pragma unroll
        for (int off = 16; off > 0; off >>= 1) v2 += __shfl_xor_sync(0xffffffffu, v2, off);
        if ((tid & 31) == 0) sRed[8 + (tid >> 5)] = v2;
        __syncthreads();
        float var = (sRed[8+g*4] + sRed[8+g*4+1] + sRed[8+g*4+2] + sRed[8+g*4+3]) * (1.0f / H);
        g_hV1[(size_t)(p0 + n) * H + c] = d * rsqrtf(var + 1e-5f) * g1[c] + be1[c];
        __syncthreads();
    }
}

// ---------------- edge update MLP + LN3 ----------------
__global__ void __launch_bounds__(256, 2)
edge_mma_kernel(const float* __restrict__ hE,
                const float* __restrict__ b12, const float* __restrict__ b13,
                const float* __restrict__ g3, const float* __restrict__ be3,
                const int* __restrict__ Eidx, float* __restrict__ outE) {
    extern __shared__ float smf[];
    float* sX   = smf;
    float* sW0  = smf + 16896;
    float* sW1  = smf + 21504;
    float* sD   = smf + 26112;
    int*   sIdx = (int*)(smf + 27136);

    const int tid = threadIdx.x;
    const int w = tid >> 5, lane = tid & 31;
    const int p0 = blockIdx.x * 8;
    const int bb = p0 >> 11;
    const int r = tid >> 1, ch = (tid & 1) * 64;
    const float* P2b = g_P2 + (size_t)bb * NN * H;

    for (int i = tid; i < 8 * H; i += 256) sD[i] = g_D2[(size_t)p0 * H + i];
    for (int i = tid; i < 8 * KNB; i += 256) sIdx[i] = Eidx[(size_t)p0 * KNB + i];

    float b13v[4], g3v[4], be3v[4];
#pragma unroll
    for (int q = 0; q < 4; q++) {
        b13v[q] = b13[lane + 32 * q];
        g3v[q]  = g3[lane + 32 * q];
        be3v[q] = be3[lane + 32 * q];
    }

    float acc[2][8][4];

    for (int t = 0; t < 3; t++) {
        const int e0 = p0 * KNB + t * 128;
        float* xr = sX + r * XP + ch;
        const float* arow = hE + (size_t)(e0 + r) * H + ch;

        __syncthreads();
#pragma unroll
        for (int c = 0; c < 64; c += 4) {
            float4 v = *(const float4*)(arow + c);
            xr[c] = to_tf32(v.x); xr[c+1] = to_tf32(v.y);
            xr[c+2] = to_tf32(v.z); xr[c+3] = to_tf32(v.w);
        }

        zero_acc(acc);
        gemm256_db(sX, sW0, sW1, g_Wt + W_11E * HH, tid, acc);
        __syncthreads();
        epi1_reg(sX, tid, t * 128, acc, P2b, sIdx + t * 128, sD);

        zero_acc(acc);
        gemm256_db(sX, sW0, sW1, g_Wt + W_12T * HH, tid, acc);
        __syncthreads();
        epi_bias_gelu(sX, tid, acc, b12);

        zero_acc(acc);
        gemm256_db(sX, sW0, sW1, g_Wt + W_13T * HH, tid, acc);
        __syncthreads();
        store_acc(sX, tid, acc);
        __syncthreads();

        // LN3 with fused b13 + hE residual: each warp 16 rows
        for (int rr = w * 16; rr < w * 16 + 16; rr++) {
            const float* he = hE + (size_t)(e0 + rr) * H;
            float v[4];
            float ssum = 0.f;
#pragma unroll
            for (int q = 0; q < 4; q++) {
                v[q] = sX[rr * XP + lane + 32 * q] + b13v[q] + he[lane + 32 * q];
                ssum += v[q];
            }
#pragma unroll
            for (int off = 16; off > 0; off >>= 1) ssum += __shfl_xor_sync(0xffffffffu, ssum, off);
            float mean = ssum * (1.0f / H);
            float vs = 0.f;
#pragma unroll
            for (int q = 0; q < 4; q++) { v[q] -= mean; vs += v[q] * v[q]; }
#pragma unroll
            for (int off = 16; off > 0; off >>= 1) vs += __shfl_xor_sync(0xffffffffu, vs, off);
            float rs = rsqrtf(vs * (1.0f / H) + 1e-5f);
#pragma unroll
            for (int q = 0; q < 4; q++)
                outE[(size_t)(e0 + rr) * H + lane + 32 * q] = v[q] * rs * g3v[q] + be3v[q];
        }
        __syncthreads();
    }
}

// ---------------- FFN (tensor): 32 nodes/CTA, grid 128 ----------------
__global__ void __launch_bounds__(256)
ffn_mma(const float* __restrict__ b_in, const float* __restrict__ b_out,
        const float* __restrict__ g2, const float* __restrict__ be2,
        const float* __restrict__ maskV, float* __restrict__ outV) {
    extern __shared__ float smf[];
    float* sXa = smf;
    float* sXb = smf + 4224;
    float* sW  = smf + 8448;
    const int tid = threadIdx.x;
    const int w = tid >> 5, lane = tid & 31;
    const int p0 = blockIdx.x * 32;

    {
        const int r = tid >> 3, c0 = (tid & 7) * 16;
        const float* a = g_hV1 + (size_t)(p0 + r) * H + c0;
        float* xa = sXa + r * XP + c0;
#pragma unroll
        for (int c = 0; c < 16; c += 4) {
            float4 v = *(const float4*)(a + c);
            xa[c] = to_tf32(v.x); xa[c+1] = to_tf32(v.y);
            xa[c+2] = to_tf32(v.z); xa[c+3] = to_tf32(v.w);
        }
    }

    float acc[2][2][4], acc2[2][2][4];
    zero_acc32(acc2);
#pragma unroll
    for (int nc = 0; nc < 4; nc++) {
        zero_acc32(acc);
        gemm32(sXa, sW, g_Wt + (W_INT + nc) * HH, tid, acc);
        __syncthreads();
        epi_bias_gelu32(sXb, tid, acc, b_in + nc * 128);
        gemm32(sXb, sW, g_Wt + (W_OUTT + nc) * HH, tid, acc2);
    }
    __syncthreads();
    store_acc32(sXb, tid, acc2);
    __syncthreads();

    for (int rr = w * 4; rr < w * 4 + 4; rr++) {
        const size_t row = p0 + rr;
        const float* res = g_hV1 + row * H;
        float u[4];
        float s = 0.f;
#pragma unroll
        for (int q = 0; q < 4; q++) {
            int c = lane + 32 * q;
            u[q] = sXb[rr * XP + c] + res[c] + b_out[c];
            s += u[q];
        }
#pragma unroll
        for (int off = 16; off > 0; off >>= 1) s += __shfl_xor_sync(0xffffffffu, s, off);
        float mean = s * (1.0f / H);
        float vs = 0.f;
#pragma unroll
        for (int q = 0; q < 4; q++) { u[q] -= mean; vs += u[q] * u[q]; }
#pragma unroll
        for (int off = 16; off > 0; off >>= 1) vs += __shfl_xor_sync(0xffffffffu, vs, off);
        float rs = rsqrtf(vs * (1.0f / H) + 1e-5f);
        float mv = maskV[row];
#pragma unroll
        for (int q = 0; q < 4; q++) {
            int c = lane + 32 * q;
            outV[row * H + c] = (u[q] * rs * g2[c] + be2[c]) * mv;
        }
    }
}

// ---------------- launch ----------------
extern "C" void kernel_launch(void* const* d_in, const int* in_sizes, int n_in,
                              void* d_out, int out_size) {
    const float* hV    = (const float*)d_in[0];
    const float* hVa   = (const float*)d_in[1];
    const float* hE    = (const float*)d_in[2];
    const float* W1    = (const float*)d_in[3];
    const float* b1    = (const float*)d_in[4];
    const float* W2    = (const float*)d_in[5];
    const float* b2    = (const float*)d_in[6];
    const float* W3    = (const float*)d_in[7];
    const float* b3    = (const float*)d_in[8];
    const float* W11   = (const float*)d_in[9];
    const float* b11   = (const float*)d_in[10];
    const float* W12   = (const float*)d_in[11];
    const float* b12   = (const float*)d_in[12];
    const float* W13   = (const float*)d_in[13];
    const float* b13   = (const float*)d_in[14];
    const float* W_in  = (const float*)d_in[15];
    const float* b_in  = (const float*)d_in[16];
    const float* W_out = (const float*)d_in[17];
    const float* b_out = (const float*)d_in[18];
    const float* g1    = (const float*)d_in[19];
    const float* be1   = (const float*)d_in[20];
    const float* g2    = (const float*)d_in[21];
    const float* be2   = (const float*)d_in[22];
    const float* g3    = (const float*)d_in[23];
    const float* be3   = (const float*)d_in[24];
    const float* maskV = (const float*)d_in[25];
    const float* maskA = (const float*)d_in[26];
    const int*   Eidx  = (const int*)d_in[27];

    const int BN = in_sizes[0] / H;   // 4096
    float* outV = (float*)d_out;
    float* outE = (float*)d_out + (size_t)BN * H;

    const size_t smemNODE = SMEM_NODE * sizeof(float);  // ~114.7 KB (2 CTAs/SM)
    const size_t smemEDGE = SMEM_EDGE * sizeof(float);  // ~110.1 KB
    const size_t smemPRE1 = 25600 * sizeof(float);      // 102.4 KB
    const size_t smemPRE2 = 17152 * sizeof(float);      // 68.6 KB
    const size_t smemFFN  = 17152 * sizeof(float);      // 68.6 KB

    cudaFuncSetAttribute(node_mma_kernel, cudaFuncAttributeMaxDynamicSharedMemorySize, (int)smemNODE);
    cudaFuncSetAttribute(edge_mma_kernel, cudaFuncAttributeMaxDynamicSharedMemorySize, (int)smemEDGE);
    cudaFuncSetAttribute(pre1_mma, cudaFuncAttributeMaxDynamicSharedMemorySize, (int)smemPRE1);
    cudaFuncSetAttribute(pre2_mma, cudaFuncAttributeMaxDynamicSharedMemorySize, (int)smemPRE2);
    cudaFuncSetAttribute(ffn_mma,  cudaFuncAttributeMaxDynamicSharedMemorySize, (int)smemFFN);

    prep_weights<<<(19 * HH + 255) / 256, 256>>>(W1, W2, W3, W11, W12, W13, W_in, W_out);
    pre1_mma<<<dim3(BN / 64, 2), 256, smemPRE1>>>(hV, hVa, b1);
    node_mma_kernel<<<BN / 8, 256, smemNODE>>>(hV, hE, b2, b3, g1, be1, maskA, Eidx);
    ffn_mma<<<BN / 32, 256, smemFFN>>>(b_in, b_out, g2, be2, maskV, outV);
    pre2_mma<<<dim3(BN / 64, 2), 256, smemPRE2>>>(outV, b11);
    edge_mma_kernel<<<BN / 8, 256, smemEDGE>>>(hE, b12, b13, g3, be3, Eidx, outE);
}

// round 16
// speedup vs baseline: 1.4599x; 1.1278x over previous
#include <cuda_runtime.h>
#include <cstdint>
#include <math.h>

#define H      128
#define HH     (H * H)
#define KNB    48
#define NN     2048
#define BNTOT  4096
#define XP     132          // activation tile pitch (floats)
#define WPQ    36           // weight quarter pitch (floats, cp.async path)

// weight matrix slots in g_Wt (all 128x128 [n][kperm], tf32-rounded)
#define W_E1   0
#define W_2T   1
#define W_3T   2
#define W_11E  3
#define W_12T  4
#define W_13T  5
#define W_1V   6
#define W_1G   7
#define W_1A   8
#define W_11V  9
#define W_11G  10
#define W_INT  11   // 11..14: W_in^T chunks
#define W_OUTT 15   // 15..18: W_out^T chunks

__device__ float g_Wt[19 * HH];
__device__ float g_D1[BNTOT * H];
__device__ float g_P1[BNTOT * H];
__device__ float g_D2[BNTOT * H];
__device__ float g_P2[BNTOT * H];
__device__ float g_hV1[BNTOT * H];

__device__ __forceinline__ float to_tf32(float x) {
    uint32_t u;
    asm("cvt.rna.tf32.f32 %0, %1;" : "=r"(u) : "f"(x));
    return __uint_as_float(u);
}

__device__ __forceinline__ float gelu_exact(float x) {
    return 0.5f * x * (1.0f + erff(x * 0.70710678118654752f));
}

__device__ __forceinline__ void mma_tf32(float d[4], const uint32_t a[4], const uint32_t b[2]) {
    asm volatile("mma.sync.aligned.m16n8k8.row.col.f32.tf32.tf32.f32 "
                 "{%0,%1,%2,%3}, {%4,%5,%6,%7}, {%8,%9}, {%0,%1,%2,%3};"
                 : "+f"(d[0]), "+f"(d[1]), "+f"(d[2]), "+f"(d[3])
                 : "r"(a[0]), "r"(a[1]), "r"(a[2]), "r"(a[3]), "r"(b[0]), "r"(b[1]));
}

// ---------------- async stage of one 32-k quarter (128n x 32k) into buf ----------------
__device__ __forceinline__ void stage_q_async(float* __restrict__ buf,
                                              const float* __restrict__ Wg, int q, int tid) {
    uint32_t base = (uint32_t)__cvta_generic_to_shared(buf);
#pragma unroll
    for (int i = 0; i < 4; i++) {
        int idx = tid + 256 * i;          // 0..1023
        int n = idx >> 3, qd = idx & 7;
        asm volatile("cp.async.cg.shared.global [%0], [%1], 16;"
                     :: "r"(base + (uint32_t)((n * WPQ + qd * 4) * 4)),
                        "l"(Wg + n * H + q * 32 + qd * 4));
    }
    asm volatile("cp.async.commit_group;");
}

// ---------------- async stage of a 128x128 activation tile (raw fp32) ----------------
__device__ __forceinline__ void stage_rows_async(float* __restrict__ sX,
                                                 const float* __restrict__ src, int tid) {
    uint32_t base = (uint32_t)__cvta_generic_to_shared(sX);
    const int r = tid >> 1, ch = (tid & 1) * 64;
    uint32_t dst = base + (uint32_t)((r * XP + ch) * 4);
    const float* s = src + (size_t)r * H + ch;
#pragma unroll
    for (int c = 0; c < 64; c += 4)
        asm volatile("cp.async.cg.shared.global [%0], [%1], 16;"
                     :: "r"(dst + (uint32_t)(c * 4)), "l"(s + c));
    asm volatile("cp.async.commit_group;");
}

// ---------------- 128x128x128 tf32 GEMM, double-buffered async staging ----------------
// 256 threads (8 warps, 4m x 2n). B is k-pair-permuted -> single float2 LDS.
__device__ __forceinline__ void gemm256_db(const float* __restrict__ sX,
                                           float* __restrict__ sW0, float* __restrict__ sW1,
                                           const float* __restrict__ Wg, int tid,
                                           float acc[2][8][4]) {
    const int w = tid >> 5, lane = tid & 31;
    const int wm = w & 3, wn = w >> 2;
    const int lr = lane >> 2, lc = lane & 3;
    const float* sXw = sX + (wm * 32 + lr) * XP + lc;

    stage_q_async(sW0, Wg, 0, tid);
#pragma unroll
    for (int q = 0; q < 4; q++) {
        asm volatile("cp.async.wait_group 0;");
        __syncthreads();
        if (q < 3) stage_q_async((q & 1) ? sW0 : sW1, Wg, q + 1, tid);
        const float* bq = (q & 1) ? sW1 : sW0;
        const float* sWb = bq + (wn * 64 + lr) * WPQ + 2 * lc;
#pragma unroll
        for (int k8 = 0; k8 < 4; k8++) {
            const int kl = k8 * 8;
            uint32_t a[2][4];
#pragma unroll
            for (int mt = 0; mt < 2; mt++) {
                const float* ap = sXw + mt * (16 * XP) + q * 32 + kl;
                a[mt][0] = __float_as_uint(ap[0]);
                a[mt][1] = __float_as_uint(ap[8 * XP]);
                a[mt][2] = __float_as_uint(ap[4]);
                a[mt][3] = __float_as_uint(ap[8 * XP + 4]);
            }
#pragma unroll
            for (int nt = 0; nt < 8; nt++) {
                float2 bv = *(const float2*)(sWb + nt * (8 * WPQ) + kl);
                uint32_t b[2] = {__float_as_uint(bv.x), __float_as_uint(bv.y)};
                mma_tf32(acc[0][nt], a[0], b);
                mma_tf32(acc[1][nt], a[1], b);
            }
        }
    }
}

// ---------------- 64x128x128 tf32 GEMM, db async (warp tile 16x64) ----------------
__device__ __forceinline__ void gemm64_db(const float* __restrict__ sX,
                                          float* __restrict__ sW0, float* __restrict__ sW1,
                                          const float* __restrict__ Wg, int tid,
                                          float acc[8][4]) {
    const int w = tid >> 5, lane = tid & 31;
    const int wm = w & 3, wn = w >> 2;
    const int lr = lane >> 2, lc = lane & 3;
    const float* sXw = sX + (wm * 16 + lr) * XP + lc;

    stage_q_async(sW0, Wg, 0, tid);
#pragma unroll
    for (int q = 0; q < 4; q++) {
        asm volatile("cp.async.wait_group 0;");
        __syncthreads();
        if (q < 3) stage_q_async((q & 1) ? sW0 : sW1, Wg, q + 1, tid);
        const float* bq = (q & 1) ? sW1 : sW0;
        const float* sWb = bq + (wn * 64 + lr) * WPQ + 2 * lc;
#pragma unroll
        for (int k8 = 0; k8 < 4; k8++) {
            const int kl = k8 * 8;
            const float* ap = sXw + q * 32 + kl;
            uint32_t a[4];
            a[0] = __float_as_uint(ap[0]);
            a[1] = __float_as_uint(ap[8 * XP]);
            a[2] = __float_as_uint(ap[4]);
            a[3] = __float_as_uint(ap[8 * XP + 4]);
#pragma unroll
            for (int nt = 0; nt < 8; nt++) {
                float2 bv = *(const float2*)(sWb + nt * (8 * WPQ) + kl);
                uint32_t b[2] = {__float_as_uint(bv.x), __float_as_uint(bv.y)};
                mma_tf32(acc[nt], a, b);
            }
        }
    }
}

// ---------------- 32x128x128 tf32 GEMM, db async (8 warps across n) ----------------
__device__ __forceinline__ void gemm32_db(const float* __restrict__ sX,
                                          float* __restrict__ sW0, float* __restrict__ sW1,
                                          const float* __restrict__ Wg, int tid,
                                          float acc[2][2][4]) {
    const int w = tid >> 5, lane = tid & 31;
    const int lr = lane >> 2, lc = lane & 3;
    const float* sXw = sX + lr * XP + lc;

    stage_q_async(sW0, Wg, 0, tid);
#pragma unroll
    for (int q = 0; q < 4; q++) {
        asm volatile("cp.async.wait_group 0;");
        __syncthreads();
        if (q < 3) stage_q_async((q & 1) ? sW0 : sW1, Wg, q + 1, tid);
        const float* bq = (q & 1) ? sW1 : sW0;
        const float* sWb = bq + (w * 16 + lr) * WPQ + 2 * lc;
#pragma unroll
        for (int k8 = 0; k8 < 4; k8++) {
            const int kl = k8 * 8;
            uint32_t a[2][4];
#pragma unroll
            for (int mt = 0; mt < 2; mt++) {
                const float* ap = sXw + mt * (16 * XP) + q * 32 + kl;
                a[mt][0] = __float_as_uint(ap[0]);
                a[mt][1] = __float_as_uint(ap[8 * XP]);
                a[mt][2] = __float_as_uint(ap[4]);
                a[mt][3] = __float_as_uint(ap[8 * XP + 4]);
            }
#pragma unroll
            for (int nt = 0; nt < 2; nt++) {
                float2 bv = *(const float2*)(sWb + nt * (8 * WPQ) + kl);
                uint32_t b[2] = {__float_as_uint(bv.x), __float_as_uint(bv.y)};
                mma_tf32(acc[0][nt], a[0], b);
                mma_tf32(acc[1][nt], a[1], b);
            }
        }
    }
}

__device__ __forceinline__ void zero_acc(float acc[2][8][4]) {
#pragma unroll
    for (int mt = 0; mt < 2; mt++)
#pragma unroll
        for (int nt = 0; nt < 8; nt++)
#pragma unroll
            for (int q = 0; q < 4; q++) acc[mt][nt][q] = 0.f;
}

__device__ __forceinline__ void zero_acc8(float acc[8][4]) {
#pragma unroll
    for (int nt = 0; nt < 8; nt++)
#pragma unroll
        for (int q = 0; q < 4; q++) acc[nt][q] = 0.f;
}

__device__ __forceinline__ void zero_acc32(float acc[2][2][4]) {
#pragma unroll
    for (int mt = 0; mt < 2; mt++)
#pragma unroll
        for (int nt = 0; nt < 2; nt++)
#pragma unroll
            for (int q = 0; q < 4; q++) acc[mt][nt][q] = 0.f;
}

__device__ __forceinline__ void store_acc(float* __restrict__ dst, int tid,
                                          const float acc[2][8][4]) {
    const int w = tid >> 5, lane = tid & 31;
    const int wm = w & 3, wn = w >> 2;
    const int lr = lane >> 2, lc = lane & 3;
    float* cx = dst + (wm * 32 + lr) * XP + wn * 64 + 2 * lc;
#pragma unroll
    for (int mt = 0; mt < 2; mt++)
#pragma unroll
        for (int nt = 0; nt < 8; nt++) {
            *(float2*)(cx + mt * (16 * XP) + nt * 8) =
                make_float2(acc[mt][nt][0], acc[mt][nt][1]);
            *(float2*)(cx + mt * (16 * XP) + 8 * XP + nt * 8) =
                make_float2(acc[mt][nt][2], acc[mt][nt][3]);
        }
}

// register epi1: sX = gelu(acc + sD[node(row)] + P[src(row)])  (fp32; MMA truncates)
__device__ __forceinline__ void epi1_reg(float* __restrict__ sX, int tid, int t128,
                                         const float acc[2][8][4],
                                         const float* __restrict__ Pbase,
                                         const int* __restrict__ sIdxT,
                                         const float* __restrict__ sD) {
    const int w = tid >> 5, lane = tid & 31;
    const int wm = w & 3, wn = w >> 2;
    const int lr = lane >> 2, lc = lane & 3;
#pragma unroll
    for (int mt = 0; mt < 2; mt++) {
#pragma unroll
        for (int hf = 0; hf < 2; hf++) {
            int r = wm * 32 + mt * 16 + lr + hf * 8;
            int src = sIdxT[r];
            int nl = (t128 + r) / KNB;
            const float* pr = Pbase + (size_t)src * H;
            const float* dn = sD + nl * H;
            float* xrow = sX + r * XP;
            const int ai = hf * 2;
#pragma unroll
            for (int nt = 0; nt < 8; nt++) {
                int col = wn * 64 + nt * 8 + 2 * lc;
                float2 p = *(const float2*)(pr + col);
                float2 d = *(const float2*)(dn + col);
                *(float2*)(xrow + col) =
                    make_float2(gelu_exact(acc[mt][nt][ai] + d.x + p.x),
                                gelu_exact(acc[mt][nt][ai + 1] + d.y + p.y));
            }
        }
    }
}

__device__ __forceinline__ void epi_bias_gelu(float* __restrict__ dst, int tid,
                                              const float acc[2][8][4],
                                              const float* __restrict__ bias) {
    const int w = tid >> 5, lane = tid & 31;
    const int wm = w & 3, wn = w >> 2;
    const int lr = lane >> 2, lc = lane & 3;
    float* cx = dst + (wm * 32 + lr) * XP + wn * 64 + 2 * lc;
#pragma unroll
    for (int nt = 0; nt < 8; nt++) {
        float2 bv = *(const float2*)(bias + wn * 64 + nt * 8 + 2 * lc);
#pragma unroll
        for (int mt = 0; mt < 2; mt++) {
            *(float2*)(cx + mt * (16 * XP) + nt * 8) =
                make_float2(gelu_exact(acc[mt][nt][0] + bv.x),
                            gelu_exact(acc[mt][nt][1] + bv.y));
            *(float2*)(cx + mt * (16 * XP) + 8 * XP + nt * 8) =
                make_float2(gelu_exact(acc[mt][nt][2] + bv.x),
                            gelu_exact(acc[mt][nt][3] + bv.y));
        }
    }
}

__device__ __forceinline__ void epi_mask_bias(float* __restrict__ dst, int tid,
                                              const float acc[2][8][4],
                                              const float* __restrict__ bias,
                                              const float* __restrict__ sMask) {
    const int w = tid >> 5, lane = tid & 31;
    const int wm = w & 3, wn = w >> 2;
    const int lr = lane >> 2, lc = lane & 3;
    float* cx = dst + (wm * 32 + lr) * XP + wn * 64 + 2 * lc;
#pragma unroll
    for (int mt = 0; mt < 2; mt++) {
        int r0 = wm * 32 + mt * 16 + lr;
        float mk0 = sMask[r0], mk8 = sMask[r0 + 8];
#pragma unroll
        for (int nt = 0; nt < 8; nt++) {
            float2 bv = *(const float2*)(bias + wn * 64 + nt * 8 + 2 * lc);
            *(float2*)(cx + mt * (16 * XP) + nt * 8) =
                make_float2(mk0 * (acc[mt][nt][0] + bv.x), mk0 * (acc[mt][nt][1] + bv.y));
            *(float2*)(cx + mt * (16 * XP) + 8 * XP + nt * 8) =
                make_float2(mk8 * (acc[mt][nt][2] + bv.x), mk8 * (acc[mt][nt][3] + bv.y));
        }
    }
}

// 64-row epilogue: global[row][col] = acc + optional bias (fp32), rows offset p0
__device__ __forceinline__ void epi_to_global64(float* __restrict__ gdst, int p0, int tid,
                                                const float acc[8][4],
                                                const float* __restrict__ bias) {
    const int w = tid >> 5, lane = tid & 31;
    const int wm = w & 3, wn = w >> 2;
    const int lr = lane >> 2, lc = lane & 3;
    const int r0 = wm * 16 + lr;
#pragma unroll
    for (int nt = 0; nt < 8; nt++) {
        int col = wn * 64 + nt * 8 + 2 * lc;
        float2 bv = bias ? *(const float2*)(bias + col) : make_float2(0.f, 0.f);
        *(float2*)(gdst + (size_t)(p0 + r0) * H + col) =
            make_float2(acc[nt][0] + bv.x, acc[nt][1] + bv.y);
        *(float2*)(gdst + (size_t)(p0 + r0 + 8) * H + col) =
            make_float2(acc[nt][2] + bv.x, acc[nt][3] + bv.y);
    }
}

__device__ __forceinline__ void epi_bias_gelu32(float* __restrict__ dst, int tid,
                                                const float acc[2][2][4],
                                                const float* __restrict__ bias) {
    const int w = tid >> 5, lane = tid & 31;
    const int lr = lane >> 2, lc = lane & 3;
    float* cx = dst + lr * XP + w * 16 + 2 * lc;
#pragma unroll
    for (int nt = 0; nt < 2; nt++) {
        float2 bv = *(const float2*)(bias + w * 16 + nt * 8 + 2 * lc);
#pragma unroll
        for (int mt = 0; mt < 2; mt++) {
            *(float2*)(cx + mt * (16 * XP) + nt * 8) =
                make_float2(gelu_exact(acc[mt][nt][0] + bv.x),
                            gelu_exact(acc[mt][nt][1] + bv.y));
            *(float2*)(cx + mt * (16 * XP) + 8 * XP + nt * 8) =
                make_float2(gelu_exact(acc[mt][nt][2] + bv.x),
                            gelu_exact(acc[mt][nt][3] + bv.y));
        }
    }
}

__device__ __forceinline__ void store_acc32(float* __restrict__ dst, int tid,
                                            const float acc[2][2][4]) {
    const int w = tid >> 5, lane = tid & 31;
    const int lr = lane >> 2, lc = lane & 3;
    float* cx = dst + lr * XP + w * 16 + 2 * lc;
#pragma unroll
    for (int mt = 0; mt < 2; mt++)
#pragma unroll
        for (int nt = 0; nt < 2; nt++) {
            *(float2*)(cx + mt * (16 * XP) + nt * 8) =
                make_float2(acc[mt][nt][0], acc[mt][nt][1]);
            *(float2*)(cx + mt * (16 * XP) + 8 * XP + nt * 8) =
                make_float2(acc[mt][nt][2], acc[mt][nt][3]);
        }
}

// ---------------- prep weights: transpose/fold + tf32 + k-pair permutation ----------------
__global__ void prep_weights(const float* __restrict__ W1, const float* __restrict__ W2,
                             const float* __restrict__ W3, const float* __restrict__ W11,
                             const float* __restrict__ W12, const float* __restrict__ W13,
                             const float* __restrict__ W_in, const float* __restrict__ W_out) {
    int idx = blockIdx.x * 256 + threadIdx.x;
    if (idx >= 19 * HH) return;
    int m = idx / HH;
    int r = (idx >> 7) & 127;
    int c = idx & 127;
    float v;
    switch (m) {
        case W_E1:  v = W1[(128 + c) * H + r] + W1[(384 + c) * H + r]; break;
        case W_2T:  v = W2[c * H + r]; break;
        case W_3T:  v = W3[c * H + r]; break;
        case W_11E: v = W11[(128 + c) * H + r]; break;
        case W_12T: v = W12[c * H + r]; break;
        case W_13T: v = W13[c * H + r]; break;
        case W_1V:  v = W1[c * H + r]; break;
        case W_1G:  v = W1[(256 + c) * H + r]; break;
        case W_1A:  v = W1[(512 + c) * H + r]; break;
        case W_11V: v = W11[c * H + r]; break;
        case W_11G: v = W11[(256 + c) * H + r]; break;
        default:
            if (m < W_OUTT) {
                int nc = m - W_INT;
                v = W_in[c * 512 + nc * 128 + r];
            } else {
                int kc = m - W_OUTT;
                v = W_out[(kc * 128 + c) * H + r];
            }
            break;
    }
    int kperm = (c & ~7) | ((c & 3) << 1) | ((c >> 2) & 1);
    g_Wt[m * HH + r * H + kperm] = to_tf32(v);
}

// ---------------- pre1: 64-row tiles, grid (64, 2) ----------------
// smem: sXa [0..8448) | sXb [8448..16896) | sW0 [16896..21504) | sW1 [21504..26112)
__global__ void __launch_bounds__(256)
pre1_mma(const float* __restrict__ hV, const float* __restrict__ hVa,
         const float* __restrict__ b1) {
    extern __shared__ float smf[];
    float* sXa = smf;
    float* sXb = smf + 8448;
    float* sW0 = smf + 16896;
    float* sW1 = smf + 21504;
    const int tid = threadIdx.x;
    const int p0 = blockIdx.x * 64;
    const int z = blockIdx.y;
    const int r = tid >> 2, c0 = (tid & 3) * 32;

    {
        const float* a = hV + (size_t)(p0 + r) * H + c0;
        float* xa = sXa + r * XP + c0;
#pragma unroll
        for (int c = 0; c < 32; c += 4)
            *(float4*)(xa + c) = *(const float4*)(a + c);
        if (z == 1) {
            const float* b = hVa + (size_t)(p0 + r) * H + c0;
            float* xb = sXb + r * XP + c0;
#pragma unroll
            for (int c = 0; c < 32; c += 4)
                *(float4*)(xb + c) = *(const float4*)(b + c);
        }
    }

    float acc[8][4];
    zero_acc8(acc);
    if (z == 0) {
        gemm64_db(sXa, sW0, sW1, g_Wt + W_1V * HH, tid, acc);
        epi_to_global64(g_D1, p0, tid, acc, b1);
    } else {
        gemm64_db(sXa, sW0, sW1, g_Wt + W_1G * HH, tid, acc);
        gemm64_db(sXb, sW0, sW1, g_Wt + W_1A * HH, tid, acc);
        epi_to_global64(g_P1, p0, tid, acc, (const float*)nullptr);
    }
}

// ---------------- pre2: 64-row tiles, grid (64, 2) ----------------
// smem: sXa [0..8448) | sW0 [8448..13056) | sW1 [13056..17664)
__global__ void __launch_bounds__(256)
pre2_mma(const float* __restrict__ hVf, const float* __restrict__ b11) {
    extern __shared__ float smf[];
    float* sXa = smf;
    float* sW0 = smf + 8448;
    float* sW1 = smf + 13056;
    const int tid = threadIdx.x;
    const int p0 = blockIdx.x * 64;
    const int z = blockIdx.y;
    const int r = tid >> 2, c0 = (tid & 3) * 32;

    {
        const float* a = hVf + (size_t)(p0 + r) * H + c0;
        float* xa = sXa + r * XP + c0;
#pragma unroll
        for (int c = 0; c < 32; c += 4)
            *(float4*)(xa + c) = *(const float4*)(a + c);
    }

    float acc[8][4];
    zero_acc8(acc);
    if (z == 0) {
        gemm64_db(sXa, sW0, sW1, g_Wt + W_11V * HH, tid, acc);
        epi_to_global64(g_D2, p0, tid, acc, b11);
    } else {
        gemm64_db(sXa, sW0, sW1, g_Wt + W_11G * HH, tid, acc);
        epi_to_global64(g_P2, p0, tid, acc, (const float*)nullptr);
    }
}

// node smem (floats): sX 0..16896 | sW0 16896..21504 | sW1 21504..26112 |
//   sD 26112..27136 | sAcc 27136..28160 | sIdx 28160..28544 (int) |
//   sMask 28544..28672 ; sAcc2 aliases sW0 ; sRed aliases smf+18944
#define SMEM_NODE 28672
#define SMEM_EDGE 27520

// ---------------- node message MLP + sum_K + LN1 ----------------
__global__ void __launch_bounds__(256, 2)
node_mma_kernel(const float* __restrict__ hV, const float* __restrict__ hE,
                const float* __restrict__ b2, const float* __restrict__ b3,
                const float* __restrict__ g1, const float* __restrict__ be1,
                const float* __restrict__ maskA, const int* __restrict__ Eidx) {
    extern __shared__ float smf[];
    float* sX    = smf;
    float* sW0   = smf + 16896;
    float* sW1   = smf + 21504;
    float* sAcc2 = sW0;
    float* sRed  = smf + 18944;
    float* sD    = smf + 26112;
    float* sAcc  = smf + 27136;
    int*   sIdx  = (int*)(smf + 28160);
    float* sMask = smf + 28544;

    const int tid = threadIdx.x;
    const int p0 = blockIdx.x * 8;
    const int bb = p0 >> 11;
    const float* P1b = g_P1 + (size_t)bb * NN * H;

    for (int i = tid; i < 8 * H; i += 256) {
        sD[i] = g_D1[(size_t)p0 * H + i];
        sAcc[i] = 0.f;
    }
    for (int i = tid; i < 8 * KNB; i += 256) sIdx[i] = Eidx[(size_t)p0 * KNB + i];

    float acc[2][8][4];

    for (int t = 0; t < 3; t++) {
        const int e0 = p0 * KNB + t * 128;

        __syncthreads();
        stage_rows_async(sX, hE + (size_t)e0 * H, tid);   // raw fp32 tile
        if (tid < 128) sMask[tid] = maskA[e0 + tid];

        // GEMM1 + register epi1 (first wait inside gemm covers the hE group too)
        zero_acc(acc);
        gemm256_db(sX, sW0, sW1, g_Wt + W_E1 * HH, tid, acc);
        __syncthreads();
        epi1_reg(sX, tid, t * 128, acc, P1b, sIdx + t * 128, sD);

        // GEMM2 + register epi2
        zero_acc(acc);
        gemm256_db(sX, sW0, sW1, g_Wt + W_2T * HH, tid, acc);
        __syncthreads();
        epi_bias_gelu(sX, tid, acc, b2);

        // GEMM3 + register epi3 (mask)
        zero_acc(acc);
        gemm256_db(sX, sW0, sW1, g_Wt + W_3T * HH, tid, acc);
        __syncthreads();
        epi_mask_bias(sX, tid, acc, b3, sMask);
        for (int i = tid; i < 2048; i += 256) sAcc2[i] = 0.f;
        __syncthreads();

        // segment-sum rows -> per-node partials
        {
            const int col = tid & 127, half = tid >> 7;
            int rr = half * 64;
            int nl = (t * 128 + rr) / KNB;
            int nxt = (nl + 1) * KNB - t * 128;
            float a = 0.f;
            for (; rr < half * 64 + 64; rr++) {
                if (rr == nxt) { sAcc2[half * 1024 + nl * 128 + col] = a; nl++; nxt += KNB; a = 0.f; }
                a += sX[rr * XP + col];
            }
            sAcc2[half * 1024 + nl * 128 + col] = a;
        }
        __syncthreads();
        for (int i = tid; i < 1024; i += 256)
            sAcc[i] += sAcc2[i] + sAcc2[1024 + i];
    }
    __syncthreads();

    // LN1: 2 nodes at a time
    for (int step = 0; step < 4; step++) {
        const int g = tid >> 7;
        const int n = step * 2 + g;
        const int c = tid & 127;
        float u = hV[(size_t)(p0 + n) * H + c] + sAcc[n * 128 + c] * (1.0f / 30.0f);
        float s = u;
#pragma unroll
        for (int off = 16; off > 0; off >>= 1) s += __shfl_xor_sync(0xffffffffu, s, off);
        if ((tid & 31) == 0) sRed[tid >> 5] = s;
        __syncthreads();
        float mean = (sRed[g*4] + sRed[g*4+1] + sRed[g*4+2] + sRed[g*4+3]) * (1.0f / H);
        float d = u - mean;
        float v2 = d * d;
#pragma unroll
        for (int off = 16; off > 0; off >>= 1) v2 += __shfl_xor_sync(0xffffffffu, v2, off);
        if ((tid & 31) == 0) sRed[8 + (tid >> 5)] = v2;
        __syncthreads();
        float var = (sRed[8+g*4] + sRed[8+g*4+1] + sRed[8+g*4+2] + sRed[8+g*4+3]) * (1.0f / H);
        g_hV1[(size_t)(p0 + n) * H + c] = d * rsqrtf(var + 1e-5f) * g1[c] + be1[c];
        __syncthreads();
    }
}

// ---------------- edge update MLP + LN3 ----------------
__global__ void __launch_bounds__(256, 2)
edge_mma_kernel(const float* __restrict__ hE,
                const float* __restrict__ b12, const float* __restrict__ b13,
                const float* __restrict__ g3, const float* __restrict__ be3,
                const int* __restrict__ Eidx, float* __restrict__ outE) {
    extern __shared__ float smf[];
    float* sX   = smf;
    float* sW0  = smf + 16896;
    float* sW1  = smf + 21504;
    float* sD   = smf + 26112;
    int*   sIdx = (int*)(smf + 27136);

    const int tid = threadIdx.x;
    const int w = tid >> 5, lane = tid & 31;
    const int p0 = blockIdx.x * 8;
    const int bb = p0 >> 11;
    const float* P2b = g_P2 + (size_t)bb * NN * H;

    for (int i = tid; i < 8 * H; i += 256) sD[i] = g_D2[(size_t)p0 * H + i];
    for (int i = tid; i < 8 * KNB; i += 256) sIdx[i] = Eidx[(size_t)p0 * KNB + i];

    float b13v[4], g3v[4], be3v[4];
#pragma unroll
    for (int q = 0; q < 4; q++) {
        b13v[q] = b13[lane + 32 * q];
        g3v[q]  = g3[lane + 32 * q];
        be3v[q] = be3[lane + 32 * q];
    }

    float acc[2][8][4];

    for (int t = 0; t < 3; t++) {
        const int e0 = p0 * KNB + t * 128;

        __syncthreads();
        stage_rows_async(sX, hE + (size_t)e0 * H, tid);

        zero_acc(acc);
        gemm256_db(sX, sW0, sW1, g_Wt + W_11E * HH, tid, acc);
        __syncthreads();
        epi1_reg(sX, tid, t * 128, acc, P2b, sIdx + t * 128, sD);

        zero_acc(acc);
        gemm256_db(sX, sW0, sW1, g_Wt + W_12T * HH, tid, acc);
        __syncthreads();
        epi_bias_gelu(sX, tid, acc, b12);

        zero_acc(acc);
        gemm256_db(sX, sW0, sW1, g_Wt + W_13T * HH, tid, acc);
        __syncthreads();
        store_acc(sX, tid, acc);
        __syncthreads();

        // LN3 with fused b13 + hE residual: each warp 16 rows
        for (int rr = w * 16; rr < w * 16 + 16; rr++) {
            const float* he = hE + (size_t)(e0 + rr) * H;
            float v[4];
            float ssum = 0.f;
#pragma unroll
            for (int q = 0; q < 4; q++) {
                v[q] = sX[rr * XP + lane + 32 * q] + b13v[q] + he[lane + 32 * q];
                ssum += v[q];
            }
#pragma unroll
            for (int off = 16; off > 0; off >>= 1) ssum += __shfl_xor_sync(0xffffffffu, ssum, off);
            float mean = ssum * (1.0f / H);
            float vs = 0.f;
#pragma unroll
            for (int q = 0; q < 4; q++) { v[q] -= mean; vs += v[q] * v[q]; }
#pragma unroll
            for (int off = 16; off > 0; off >>= 1) vs += __shfl_xor_sync(0xffffffffu, vs, off);
            float rs = rsqrtf(vs * (1.0f / H) + 1e-5f);
#pragma unroll
            for (int q = 0; q < 4; q++)
                outE[(size_t)(e0 + rr) * H + lane + 32 * q] = v[q] * rs * g3v[q] + be3v[q];
        }
        __syncthreads();
    }
}

// ---------------- FFN (tensor): 32 nodes/CTA, grid 128 ----------------
// smem: sXa [0..4224) | sXb [4224..8448) | sW0 [8448..13056) | sW1 [13056..17664)
__global__ void __launch_bounds__(256)
ffn_mma(const float* __restrict__ b_in, const float* __restrict__ b_out,
        const float* __restrict__ g2, const float* __restrict__ be2,
        const float* __restrict__ maskV, float* __restrict__ outV) {
    extern __shared__ float smf[];
    float* sXa = smf;
    float* sXb = smf + 4224;
    float* sW0 = smf + 8448;
    float* sW1 = smf + 13056;
    const int tid = threadIdx.x;
    const int w = tid >> 5, lane = tid & 31;
    const int p0 = blockIdx.x * 32;

    {
        const int r = tid >> 3, c0 = (tid & 7) * 16;
        const float* a = g_hV1 + (size_t)(p0 + r) * H + c0;
        float* xa = sXa + r * XP + c0;
#pragma unroll
        for (int c = 0; c < 16; c += 4)
            *(float4*)(xa + c) = *(const float4*)(a + c);
    }

    float acc[2][2][4], acc2[2][2][4];
    zero_acc32(acc2);
#pragma unroll
    for (int nc = 0; nc < 4; nc++) {
        zero_acc32(acc);
        gemm32_db(sXa, sW0, sW1, g_Wt + (W_INT + nc) * HH, tid, acc);
        __syncthreads();
        epi_bias_gelu32(sXb, tid, acc, b_in + nc * 128);
        gemm32_db(sXb, sW0, sW1, g_Wt + (W_OUTT + nc) * HH, tid, acc2);
    }
    __syncthreads();
    store_acc32(sXb, tid, acc2);
    __syncthreads();

    for (int rr = w * 4; rr < w * 4 + 4; rr++) {
        const size_t row = p0 + rr;
        const float* res = g_hV1 + row * H;
        float u[4];
        float s = 0.f;
#pragma unroll
        for (int q = 0; q < 4; q++) {
            int c = lane + 32 * q;
            u[q] = sXb[rr * XP + c] + res[c] + b_out[c];
            s += u[q];
        }
#pragma unroll
        for (int off = 16; off > 0; off >>= 1) s += __shfl_xor_sync(0xffffffffu, s, off);
        float mean = s * (1.0f / H);
        float vs = 0.f;
#pragma unroll
        for (int q = 0; q < 4; q++) { u[q] -= mean; vs += u[q] * u[q]; }
#pragma unroll
        for (int off = 16; off > 0; off >>= 1) vs += __shfl_xor_sync(0xffffffffu, vs, off);
        float rs = rsqrtf(vs * (1.0f / H) + 1e-5f);
        float mv = maskV[row];
#pragma unroll
        for (int q = 0; q < 4; q++) {
            int c = lane + 32 * q;
            outV[row * H + c] = (u[q] * rs * g2[c] + be2[c]) * mv;
        }
    }
}

// ---------------- launch ----------------
extern "C" void kernel_launch(void* const* d_in, const int* in_sizes, int n_in,
                              void* d_out, int out_size) {
    const float* hV    = (const float*)d_in[0];
    const float* hVa   = (const float*)d_in[1];
    const float* hE    = (const float*)d_in[2];
    const float* W1    = (const float*)d_in[3];
    const float* b1    = (const float*)d_in[4];
    const float* W2    = (const float*)d_in[5];
    const float* b2    = (const float*)d_in[6];
    const float* W3    = (const float*)d_in[7];
    const float* b3    = (const float*)d_in[8];
    const float* W11   = (const float*)d_in[9];
    const float* b11   = (const float*)d_in[10];
    const float* W12   = (const float*)d_in[11];
    const float* b12   = (const float*)d_in[12];
    const float* W13   = (const float*)d_in[13];
    const float* b13   = (const float*)d_in[14];
    const float* W_in  = (const float*)d_in[15];
    const float* b_in  = (const float*)d_in[16];
    const float* W_out = (const float*)d_in[17];
    const float* b_out = (const float*)d_in[18];
    const float* g1    = (const float*)d_in[19];
    const float* be1   = (const float*)d_in[20];
    const float* g2    = (const float*)d_in[21];
    const float* be2   = (const float*)d_in[22];
    const float* g3    = (const float*)d_in[23];
    const float* be3   = (const float*)d_in[24];
    const float* maskV = (const float*)d_in[25];
    const float* maskA = (const float*)d_in[26];
    const int*   Eidx  = (const int*)d_in[27];

    const int BN = in_sizes[0] / H;   // 4096
    float* outV = (float*)d_out;
    float* outE = (float*)d_out + (size_t)BN * H;

    const size_t smemNODE = SMEM_NODE * sizeof(float);  // ~114.7 KB (2 CTAs/SM)
    const size_t smemEDGE = SMEM_EDGE * sizeof(float);  // ~110.1 KB
    const size_t smemPRE1 = 26112 * sizeof(float);      // 104.4 KB
    const size_t smemPRE2 = 17664 * sizeof(float);      // 70.7 KB
    const size_t smemFFN  = 17664 * sizeof(float);      // 70.7 KB

    cudaFuncSetAttribute(node_mma_kernel, cudaFuncAttributeMaxDynamicSharedMemorySize, (int)smemNODE);
    cudaFuncSetAttribute(edge_mma_kernel, cudaFuncAttributeMaxDynamicSharedMemorySize, (int)smemEDGE);
    cudaFuncSetAttribute(pre1_mma, cudaFuncAttributeMaxDynamicSharedMemorySize, (int)smemPRE1);
    cudaFuncSetAttribute(pre2_mma, cudaFuncAttributeMaxDynamicSharedMemorySize, (int)smemPRE2);
    cudaFuncSetAttribute(ffn_mma,  cudaFuncAttributeMaxDynamicSharedMemorySize, (int)smemFFN);

    prep_weights<<<(19 * HH + 255) / 256, 256>>>(W1, W2, W3, W11, W12, W13, W_in, W_out);
    pre1_mma<<<dim3(BN / 64, 2), 256, smemPRE1>>>(hV, hVa, b1);
    node_mma_kernel<<<BN / 8, 256, smemNODE>>>(hV, hE, b2, b3, g1, be1, maskA, Eidx);
    ffn_mma<<<BN / 32, 256, smemFFN>>>(b_in, b_out, g2, be2, maskV, outV);
    pre2_mma<<<dim3(BN / 64, 2), 256, smemPRE2>>>(outV, b11);
    edge_mma_kernel<<<BN / 8, 256, smemEDGE>>>(hE, b12, b13, g3, be3, Eidx, outE);
}